// round 8
// baseline (speedup 1.0000x reference)
#include <cuda_runtime.h>

#define BB  32
#define NN  16384
#define DD  64
#define NSL 7
#define HH  128

// ---- scratch (device globals; no allocations allowed) ----
__device__ float g_k[(size_t)BB*NN*DD];   // 128 MB
__device__ float g_v[(size_t)BB*NN*DD];   // 128 MB
__device__ float g_slots[BB*NSL*DD];
__device__ float g_q[BB*NSL*DD];
__device__ float g_U[BB*NSL*DD];
__device__ float g_S[BB*NSL];

// ============================================================
// Projection: x = LN(inputs); k = x@Wk.T + bk; v = x@Wv.T + bv
// grid 2048 blocks x 256 thr; each block: 256 rows (8 tiles of 32)
// ============================================================
__global__ void __launch_bounds__(256) proj_kernel(
    const float* __restrict__ inp,
    const float* __restrict__ Wk, const float* __restrict__ bk,
    const float* __restrict__ Wv, const float* __restrict__ bv,
    const float* __restrict__ gin, const float* __restrict__ bin)
{
    __shared__ float WkT[64*64];
    __shared__ float WvT[64*64];
    __shared__ __align__(16) float xT[64*36];
    __shared__ float gi[64], bi[64], bkv[128];

    int t = threadIdx.x;
    for (int e = t; e < 4096; e += 256) {
        int d = e >> 6, j = e & 63;
        WkT[j*64 + d] = Wk[e];
        WvT[j*64 + d] = Wv[e];
    }
    if (t < 64) { gi[t] = gin[t]; bi[t] = bin[t]; bkv[t] = bk[t]; bkv[64+t] = bv[t]; }
    __syncthreads();

    int w = t >> 5, lane = t & 31;
    int og = w & 3, rh = w >> 2;
    const float* WT = (og < 2) ? WkT : WvT;
    int col = lane + 32*(og & 1);
    float* outbase = (og < 2) ? g_k : g_v;
    float bias = bkv[((og < 2) ? 0 : 64) + col];

    int r  = t >> 3;        // 0..31 row within tile (for LN phase)
    int j0 = t & 7;

    for (int tile = 0; tile < 8; tile++) {
        size_t row0 = (size_t)blockIdx.x*256 + (size_t)tile*32;

        // ---- LN: 8 threads per row, values kept in regs ----
        {
            const float* xrow = inp + (row0 + r)*DD;
            float xr[8];
            float s = 0.f, ss = 0.f;
            #pragma unroll
            for (int jj = 0; jj < 8; jj++) {
                float x = xrow[j0 + 8*jj];
                xr[jj] = x; s += x; ss += x*x;
            }
            #pragma unroll
            for (int m = 1; m <= 4; m <<= 1) {
                s  += __shfl_xor_sync(0xffffffffu, s,  m);
                ss += __shfl_xor_sync(0xffffffffu, ss, m);
            }
            float mean = s * (1.f/64.f);
            float var  = ss * (1.f/64.f) - mean*mean;
            float rstd = rsqrtf(var + 1e-5f);
            #pragma unroll
            for (int jj = 0; jj < 8; jj++) {
                int j = j0 + 8*jj;
                xT[j*36 + r] = (xr[jj] - mean)*rstd*gi[j] + bi[j];
            }
        }
        __syncthreads();

        // ---- GEMM: 16 rows x 1 col per lane ----
        float acc[16];
        #pragma unroll
        for (int i = 0; i < 16; i++) acc[i] = bias;
        #pragma unroll 8
        for (int j = 0; j < 64; j++) {
            float wv = WT[j*64 + col];
            const float4* xp = (const float4*)&xT[j*36 + rh*16];
            float4 a = xp[0], b2 = xp[1], c2 = xp[2], d2 = xp[3];
            acc[0]  = fmaf(wv, a.x,  acc[0]);  acc[1]  = fmaf(wv, a.y,  acc[1]);
            acc[2]  = fmaf(wv, a.z,  acc[2]);  acc[3]  = fmaf(wv, a.w,  acc[3]);
            acc[4]  = fmaf(wv, b2.x, acc[4]);  acc[5]  = fmaf(wv, b2.y, acc[5]);
            acc[6]  = fmaf(wv, b2.z, acc[6]);  acc[7]  = fmaf(wv, b2.w, acc[7]);
            acc[8]  = fmaf(wv, c2.x, acc[8]);  acc[9]  = fmaf(wv, c2.y, acc[9]);
            acc[10] = fmaf(wv, c2.z, acc[10]); acc[11] = fmaf(wv, c2.w, acc[11]);
            acc[12] = fmaf(wv, d2.x, acc[12]); acc[13] = fmaf(wv, d2.y, acc[13]);
            acc[14] = fmaf(wv, d2.z, acc[14]); acc[15] = fmaf(wv, d2.w, acc[15]);
        }
        float* dst = outbase + (row0 + (size_t)rh*16)*DD + col;
        #pragma unroll
        for (int rr = 0; rr < 16; rr++) dst[(size_t)rr*DD] = acc[rr];
        __syncthreads();
    }
}

// ============================================================
// Attention pass (one iteration): streaming over keys.
// grid (16 chunks, B), 256 thr, 1024 keys/block (4 tiles of 256).
// ============================================================
__global__ void __launch_bounds__(256) attn_kernel()
{
    int b = blockIdx.y;
    int t = threadIdx.x;
    __shared__ __align__(16) float q_sh[NSL*DD];
    __shared__ __align__(16) float attn_sh[256][8];
    __shared__ float S_sh[NSL];

    for (int e = t; e < NSL*DD; e += 256) q_sh[e] = g_q[b*NSL*DD + e];   // FIX: 448 > 256
    if (t < NSL) S_sh[t] = 0.f;
    __syncthreads();

    float S_loc[NSL], U_loc[NSL];
    #pragma unroll
    for (int i = 0; i < NSL; i++) { S_loc[i] = 0.f; U_loc[i] = 0.f; }

    int g = t >> 6, d = t & 63;
    int base = blockIdx.x * 1024;

    for (int tile = 0; tile < 4; tile++) {
        int jb = base + tile*256;
        // ---- phase A: thread <-> key ----
        const float4* kp = (const float4*)(g_k + ((size_t)b*NN + jb + t)*DD);
        float acc[NSL];
        #pragma unroll
        for (int i = 0; i < NSL; i++) acc[i] = 0.f;
        #pragma unroll
        for (int c = 0; c < 16; c++) {
            float4 kk = kp[c];
            #pragma unroll
            for (int i = 0; i < NSL; i++) {
                float4 qq = ((const float4*)q_sh)[i*16 + c];
                acc[i] = fmaf(qq.x, kk.x, acc[i]);
                acc[i] = fmaf(qq.y, kk.y, acc[i]);
                acc[i] = fmaf(qq.z, kk.z, acc[i]);
                acc[i] = fmaf(qq.w, kk.w, acc[i]);
            }
        }
        float mx = acc[0];
        #pragma unroll
        for (int i = 1; i < NSL; i++) mx = fmaxf(mx, acc[i]);
        float e[8]; float ssum = 0.f;
        #pragma unroll
        for (int i = 0; i < NSL; i++) { e[i] = __expf(acc[i] - mx); ssum += e[i]; }
        float inv = __fdividef(1.f, ssum);
        #pragma unroll
        for (int i = 0; i < NSL; i++) {
            float p = fmaf(e[i], inv, 1e-8f);   // softmax + EPS
            e[i] = p; S_loc[i] += p;
        }
        e[7] = 0.f;
        *(float4*)&attn_sh[t][0] = make_float4(e[0], e[1], e[2], e[3]);
        *(float4*)&attn_sh[t][4] = make_float4(e[4], e[5], e[6], e[7]);
        __syncthreads();

        // ---- phase B: thread <-> (key-group, d); coalesced v reads ----
        const float* vp = g_v + ((size_t)b*NN + jb + g*64)*DD + d;
        #pragma unroll 4
        for (int jj = 0; jj < 64; jj++) {
            float va = vp[(size_t)jj*DD];
            int jl = g*64 + jj;
            float4 a0 = *(const float4*)&attn_sh[jl][0];
            float4 a1 = *(const float4*)&attn_sh[jl][4];
            U_loc[0] = fmaf(a0.x, va, U_loc[0]);
            U_loc[1] = fmaf(a0.y, va, U_loc[1]);
            U_loc[2] = fmaf(a0.z, va, U_loc[2]);
            U_loc[3] = fmaf(a0.w, va, U_loc[3]);
            U_loc[4] = fmaf(a1.x, va, U_loc[4]);
            U_loc[5] = fmaf(a1.y, va, U_loc[5]);
            U_loc[6] = fmaf(a1.z, va, U_loc[6]);
        }
        __syncthreads();
    }

    // ---- reduce S within block, then one global atomic per slot ----
    #pragma unroll
    for (int i = 0; i < NSL; i++) {
        float sv = S_loc[i];
        #pragma unroll
        for (int m = 16; m >= 1; m >>= 1) sv += __shfl_xor_sync(0xffffffffu, sv, m);
        if ((t & 31) == 0) atomicAdd(&S_sh[i], sv);
    }
    __syncthreads();
    if (t < NSL) atomicAdd(&g_S[b*NSL + t], S_sh[t]);
    #pragma unroll
    for (int i = 0; i < NSL; i++)
        atomicAdd(&g_U[(b*NSL + i)*DD + d], U_loc[i]);
}

// ============================================================
// Prep: slots0 = mu + sigma*noise; zero S/U; q0 = LN(slots0)@Wq.T+bq, *scale
// launched with 448 threads (= NSL*DD)
// ============================================================
__global__ void __launch_bounds__(448) prep_kernel(
    const float* __restrict__ noise, const float* __restrict__ mu,
    const float* __restrict__ sigma,
    const float* __restrict__ Wq, const float* __restrict__ bq,
    const float* __restrict__ gsl, const float* __restrict__ bsl)
{
    int b = blockIdx.x, t = threadIdx.x;
    __shared__ float sl[NSL*DD], sn[NSL*DD];
    __shared__ float mstat[NSL][2];
    if (t < NSL*DD) {
        int d = t & 63;
        float v = mu[d] + sigma[d]*noise[b*NSL*DD + t];
        sl[t] = v;
        g_slots[b*NSL*DD + t] = v;
        g_U[b*NSL*DD + t] = 0.f;
    }
    if (t < NSL) g_S[b*NSL + t] = 0.f;
    __syncthreads();
    if (t < NSL) {
        float s = 0.f, ss = 0.f;
        for (int j = 0; j < DD; j++) { float x = sl[t*DD + j]; s += x; ss += x*x; }
        float mean = s*(1.f/64.f), var = ss*(1.f/64.f) - mean*mean;
        mstat[t][0] = mean; mstat[t][1] = rsqrtf(var + 1e-5f);
    }
    __syncthreads();
    if (t < NSL*DD) {
        int i = t >> 6, d = t & 63;
        sn[t] = (sl[t] - mstat[i][0])*mstat[i][1]*gsl[d] + bsl[d];
    }
    __syncthreads();
    if (t < NSL*DD) {
        int i = t >> 6, d = t & 63;
        float q = bq[d];
        for (int j = 0; j < DD; j++) q = fmaf(sn[i*DD + j], Wq[d*DD + j], q);
        g_q[b*NSL*DD + t] = q * 0.125f;
    }
}

// ============================================================
// Finish (per iteration): updates = U/S; GRU; residual MLP;
// write slots (+ d_out on last iter); zero S/U; next q.
// launched with 448 threads (= NSL*DD)
// ============================================================
__global__ void __launch_bounds__(448) finish_kernel(
    const float* __restrict__ W_ih, const float* __restrict__ W_hh,
    const float* __restrict__ b_ih, const float* __restrict__ b_hh,
    const float* __restrict__ mW1, const float* __restrict__ mb1,
    const float* __restrict__ mW2, const float* __restrict__ mb2,
    const float* __restrict__ gml, const float* __restrict__ bml,
    const float* __restrict__ Wq,  const float* __restrict__ bq,
    const float* __restrict__ gsl, const float* __restrict__ bsl,
    float* __restrict__ out, int is_last)
{
    int b = blockIdx.x, t = threadIdx.x;
    __shared__ float upd[NSL*DD], prev[NSL*DD];
    __shared__ float xg[NSL*192], hg[NSL*192];
    __shared__ float snew[NSL*DD], mn[NSL*DD], hid[NSL*HH], sfin[NSL*DD], sn[NSL*DD];
    __shared__ float mstat[NSL][2];

    if (t < NSL*DD) {
        int i = t >> 6;
        float S = g_S[b*NSL + i];
        upd[t]  = g_U[b*NSL*DD + t] / S;
        prev[t] = g_slots[b*NSL*DD + t];
    }
    __syncthreads();
    if (t < NSL*DD) g_U[b*NSL*DD + t] = 0.f;   // re-arm for next iter/replay
    if (t < NSL)    g_S[b*NSL + t]   = 0.f;

    // GRU gates
    for (int o = t; o < NSL*192; o += 448) {
        int i = o / 192, gd = o % 192;
        float xa = b_ih[gd], ha = b_hh[gd];
        const float* wi = W_ih + gd*DD;
        const float* wh = W_hh + gd*DD;
        const float* u  = upd  + i*DD;
        const float* p  = prev + i*DD;
        for (int j = 0; j < DD; j++) {
            xa = fmaf(u[j], wi[j], xa);
            ha = fmaf(p[j], wh[j], ha);
        }
        xg[o] = xa; hg[o] = ha;
    }
    __syncthreads();
    if (t < NSL*DD) {
        int i = t >> 6, d = t & 63;
        int b0 = i*192;
        float r = 1.f/(1.f + expf(-(xg[b0 + d]       + hg[b0 + d])));
        float z = 1.f/(1.f + expf(-(xg[b0 + 64 + d]  + hg[b0 + 64 + d])));
        float n = tanhf(xg[b0 + 128 + d] + r*hg[b0 + 128 + d]);
        snew[t] = (1.f - z)*n + z*prev[t];
    }
    __syncthreads();

    // LN (gml) -> mn
    if (t < NSL) {
        float s = 0.f, ss = 0.f;
        for (int j = 0; j < DD; j++) { float x = snew[t*DD + j]; s += x; ss += x*x; }
        float mean = s*(1.f/64.f), var = ss*(1.f/64.f) - mean*mean;
        mstat[t][0] = mean; mstat[t][1] = rsqrtf(var + 1e-5f);
    }
    __syncthreads();
    if (t < NSL*DD) {
        int i = t >> 6, d = t & 63;
        mn[t] = (snew[t] - mstat[i][0])*mstat[i][1]*gml[d] + bml[d];
    }
    __syncthreads();

    // MLP hidden
    for (int o = t; o < NSL*HH; o += 448) {
        int i = o / HH, hh = o % HH;
        float a = mb1[hh];
        const float* w1 = mW1 + hh*DD;
        const float* m  = mn + i*DD;
        for (int j = 0; j < DD; j++) a = fmaf(m[j], w1[j], a);
        hid[o] = fmaxf(a, 0.f);
    }
    __syncthreads();
    if (t < NSL*DD) {
        int i = t >> 6, d = t & 63;
        float a = mb2[d];
        const float* w2 = mW2 + d*HH;
        const float* hb = hid + i*HH;
        for (int j = 0; j < HH; j++) a = fmaf(hb[j], w2[j], a);
        float v = snew[t] + a;
        sfin[t] = v;
        g_slots[b*NSL*DD + t] = v;
        if (is_last) out[b*NSL*DD + t] = v;
    }
    __syncthreads();

    // next q = LN(sfin, gsl)@Wq.T + bq, pre-scaled
    if (t < NSL) {
        float s = 0.f, ss = 0.f;
        for (int j = 0; j < DD; j++) { float x = sfin[t*DD + j]; s += x; ss += x*x; }
        float mean = s*(1.f/64.f), var = ss*(1.f/64.f) - mean*mean;
        mstat[t][0] = mean; mstat[t][1] = rsqrtf(var + 1e-5f);
    }
    __syncthreads();
    if (t < NSL*DD) {
        int i = t >> 6, d = t & 63;
        sn[t] = (sfin[t] - mstat[i][0])*mstat[i][1]*gsl[d] + bsl[d];
    }
    __syncthreads();
    if (t < NSL*DD) {
        int i = t >> 6, d = t & 63;
        float q = bq[d];
        for (int j = 0; j < DD; j++) q = fmaf(sn[i*DD + j], Wq[d*DD + j], q);
        g_q[b*NSL*DD + t] = q * 0.125f;
    }
}

// ============================================================
extern "C" void kernel_launch(void* const* d_in, const int* in_sizes, int n_in,
                              void* d_out, int out_size)
{
    const float* inputs = (const float*)d_in[0];
    const float* noise  = (const float*)d_in[1];
    const float* mu     = (const float*)d_in[2];
    const float* sigma  = (const float*)d_in[3];
    const float* Wq     = (const float*)d_in[4];
    const float* bq     = (const float*)d_in[5];
    const float* Wk     = (const float*)d_in[6];
    const float* bk     = (const float*)d_in[7];
    const float* Wv     = (const float*)d_in[8];
    const float* bv     = (const float*)d_in[9];
    const float* W_ih   = (const float*)d_in[10];
    const float* W_hh   = (const float*)d_in[11];
    const float* b_ih   = (const float*)d_in[12];
    const float* b_hh   = (const float*)d_in[13];
    const float* mW1    = (const float*)d_in[14];
    const float* mb1    = (const float*)d_in[15];
    const float* mW2    = (const float*)d_in[16];
    const float* mb2    = (const float*)d_in[17];
    const float* gin    = (const float*)d_in[18];
    const float* bin    = (const float*)d_in[19];
    const float* gsl    = (const float*)d_in[20];
    const float* bsl    = (const float*)d_in[21];
    const float* gml    = (const float*)d_in[22];
    const float* bml    = (const float*)d_in[23];
    float* out = (float*)d_out;

    proj_kernel<<<2048, 256>>>(inputs, Wk, bk, Wv, bv, gin, bin);
    prep_kernel<<<BB, 448>>>(noise, mu, sigma, Wq, bq, gsl, bsl);
    for (int it = 0; it < 3; it++) {
        attn_kernel<<<dim3(16, BB), 256>>>();
        finish_kernel<<<BB, 448>>>(W_ih, W_hh, b_ih, b_hh, mW1, mb1, mW2, mb2,
                                   gml, bml, Wq, bq, gsl, bsl, out, (it == 2) ? 1 : 0);
    }
}

// round 9
// speedup vs baseline: 1.4729x; 1.4729x over previous
#include <cuda_runtime.h>

#define BB  32
#define NN  16384
#define DD  64
#define NSL 7
#define HH  128

// ---- scratch (device globals; no allocations allowed) ----
__device__ float g_k[(size_t)BB*NN*DD];   // 128 MB
__device__ float g_v[(size_t)BB*NN*DD];   // 128 MB
__device__ float g_slots[BB*NSL*DD];
__device__ float g_q[BB*NSL*DD];
__device__ float g_U[BB*NSL*DD];
__device__ float g_S[BB*NSL];

__device__ __forceinline__ float wred(float v) {
    v += __shfl_xor_sync(0xffffffffu, v, 16);
    v += __shfl_xor_sync(0xffffffffu, v, 8);
    v += __shfl_xor_sync(0xffffffffu, v, 4);
    v += __shfl_xor_sync(0xffffffffu, v, 2);
    v += __shfl_xor_sync(0xffffffffu, v, 1);
    return v;
}

// ============================================================
// Projection: x = LN(inputs); k = x@Wk.T + bk; v = x@Wv.T + bv
// grid 2048 blocks x 256 thr; each block: 256 rows (8 tiles of 32)
// Inner GEMM uses packed fma.rn.f32x2 (FFMA2): 8 packed FMAs/j.
// ============================================================
__global__ void __launch_bounds__(256) proj_kernel(
    const float* __restrict__ inp,
    const float* __restrict__ Wk, const float* __restrict__ bk,
    const float* __restrict__ Wv, const float* __restrict__ bv,
    const float* __restrict__ gin, const float* __restrict__ bin)
{
    __shared__ float WkT[64*64];
    __shared__ float WvT[64*64];
    __shared__ __align__(16) float xT[64*36];
    __shared__ float gi[64], bi[64], bkv[128];

    int t = threadIdx.x;
    for (int e = t; e < 4096; e += 256) {
        int d = e >> 6, j = e & 63;
        WkT[j*64 + d] = Wk[e];
        WvT[j*64 + d] = Wv[e];
    }
    if (t < 64) { gi[t] = gin[t]; bi[t] = bin[t]; bkv[t] = bk[t]; bkv[64+t] = bv[t]; }
    __syncthreads();

    int w = t >> 5, lane = t & 31;
    int og = w & 3, rh = w >> 2;
    const float* WT = (og < 2) ? WkT : WvT;
    int col = lane + 32*(og & 1);
    float* outbase = (og < 2) ? g_k : g_v;
    float bias = bkv[((og < 2) ? 0 : 64) + col];

    int r  = t >> 3;        // 0..31 row within tile (for LN phase)
    int j0 = t & 7;

    unsigned long long biasP;
    asm("mov.b64 %0, {%1, %1};" : "=l"(biasP) : "f"(bias));

    for (int tile = 0; tile < 8; tile++) {
        size_t row0 = (size_t)blockIdx.x*256 + (size_t)tile*32;

        // ---- LN: 8 threads per row, values kept in regs ----
        {
            const float* xrow = inp + (row0 + r)*DD;
            float xr[8];
            float s = 0.f, ss = 0.f;
            #pragma unroll
            for (int jj = 0; jj < 8; jj++) {
                float x = xrow[j0 + 8*jj];
                xr[jj] = x; s += x; ss += x*x;
            }
            #pragma unroll
            for (int m = 1; m <= 4; m <<= 1) {
                s  += __shfl_xor_sync(0xffffffffu, s,  m);
                ss += __shfl_xor_sync(0xffffffffu, ss, m);
            }
            float mean = s * (1.f/64.f);
            float var  = ss * (1.f/64.f) - mean*mean;
            float rstd = rsqrtf(var + 1e-5f);
            #pragma unroll
            for (int jj = 0; jj < 8; jj++) {
                int j = j0 + 8*jj;
                xT[j*36 + r] = (xr[jj] - mean)*rstd*gi[j] + bi[j];
            }
        }
        __syncthreads();

        // ---- GEMM: 16 rows x 1 col per lane, packed f32x2 ----
        unsigned long long accP[8];
        #pragma unroll
        for (int i = 0; i < 8; i++) accP[i] = biasP;
        #pragma unroll 8
        for (int j = 0; j < 64; j++) {
            float wv = WT[j*64 + col];
            unsigned long long wv2;
            asm("mov.b64 %0, {%1, %1};" : "=l"(wv2) : "f"(wv));
            const ulonglong2* xp = (const ulonglong2*)&xT[j*36 + rh*16];
            ulonglong2 xA = xp[0], xB = xp[1];
            asm("fma.rn.f32x2 %0, %1, %2, %0;" : "+l"(accP[0]) : "l"(wv2), "l"(xA.x));
            asm("fma.rn.f32x2 %0, %1, %2, %0;" : "+l"(accP[1]) : "l"(wv2), "l"(xA.y));
            asm("fma.rn.f32x2 %0, %1, %2, %0;" : "+l"(accP[2]) : "l"(wv2), "l"(xB.x));
            asm("fma.rn.f32x2 %0, %1, %2, %0;" : "+l"(accP[3]) : "l"(wv2), "l"(xB.y));
            const ulonglong2* xq = (const ulonglong2*)&xT[j*36 + rh*16 + 8];
            ulonglong2 xC = xq[0], xD = xq[1];
            asm("fma.rn.f32x2 %0, %1, %2, %0;" : "+l"(accP[4]) : "l"(wv2), "l"(xC.x));
            asm("fma.rn.f32x2 %0, %1, %2, %0;" : "+l"(accP[5]) : "l"(wv2), "l"(xC.y));
            asm("fma.rn.f32x2 %0, %1, %2, %0;" : "+l"(accP[6]) : "l"(wv2), "l"(xD.x));
            asm("fma.rn.f32x2 %0, %1, %2, %0;" : "+l"(accP[7]) : "l"(wv2), "l"(xD.y));
        }
        float* dst = outbase + (row0 + (size_t)rh*16)*DD + col;
        #pragma unroll
        for (int i = 0; i < 8; i++) {
            float lo, hi;
            asm("mov.b64 {%0, %1}, %2;" : "=f"(lo), "=f"(hi) : "l"(accP[i]));
            dst[(size_t)(2*i)*DD]   = lo;
            dst[(size_t)(2*i+1)*DD] = hi;
        }
        __syncthreads();
    }
}

// ============================================================
// Attention pass (one iteration): streaming over keys.
// grid (16 chunks, B), 256 thr, 1024 keys/block (4 tiles of 256).
// ============================================================
__global__ void __launch_bounds__(256) attn_kernel()
{
    int b = blockIdx.y;
    int t = threadIdx.x;
    __shared__ __align__(16) float q_sh[NSL*DD];
    __shared__ __align__(16) float attn_sh[256][8];
    __shared__ float S_sh[NSL];

    for (int e = t; e < NSL*DD; e += 256) q_sh[e] = g_q[b*NSL*DD + e];
    if (t < NSL) S_sh[t] = 0.f;
    __syncthreads();

    float S_loc[NSL], U_loc[NSL];
    #pragma unroll
    for (int i = 0; i < NSL; i++) { S_loc[i] = 0.f; U_loc[i] = 0.f; }

    int g = t >> 6, d = t & 63;
    int base = blockIdx.x * 1024;

    for (int tile = 0; tile < 4; tile++) {
        int jb = base + tile*256;
        // ---- phase A: thread <-> key ----
        const float4* kp = (const float4*)(g_k + ((size_t)b*NN + jb + t)*DD);
        float acc[NSL];
        #pragma unroll
        for (int i = 0; i < NSL; i++) acc[i] = 0.f;
        #pragma unroll
        for (int c = 0; c < 16; c++) {
            float4 kk = kp[c];
            #pragma unroll
            for (int i = 0; i < NSL; i++) {
                float4 qq = ((const float4*)q_sh)[i*16 + c];
                acc[i] = fmaf(qq.x, kk.x, acc[i]);
                acc[i] = fmaf(qq.y, kk.y, acc[i]);
                acc[i] = fmaf(qq.z, kk.z, acc[i]);
                acc[i] = fmaf(qq.w, kk.w, acc[i]);
            }
        }
        float mx = acc[0];
        #pragma unroll
        for (int i = 1; i < NSL; i++) mx = fmaxf(mx, acc[i]);
        float e[8]; float ssum = 0.f;
        #pragma unroll
        for (int i = 0; i < NSL; i++) { e[i] = __expf(acc[i] - mx); ssum += e[i]; }
        float inv = __fdividef(1.f, ssum);
        #pragma unroll
        for (int i = 0; i < NSL; i++) {
            float p = fmaf(e[i], inv, 1e-8f);   // softmax + EPS
            e[i] = p; S_loc[i] += p;
        }
        e[7] = 0.f;
        *(float4*)&attn_sh[t][0] = make_float4(e[0], e[1], e[2], e[3]);
        *(float4*)&attn_sh[t][4] = make_float4(e[4], e[5], e[6], e[7]);
        __syncthreads();

        // ---- phase B: thread <-> (key-group, d); coalesced v reads ----
        const float* vp = g_v + ((size_t)b*NN + jb + g*64)*DD + d;
        #pragma unroll 4
        for (int jj = 0; jj < 64; jj++) {
            float va = vp[(size_t)jj*DD];
            int jl = g*64 + jj;
            float4 a0 = *(const float4*)&attn_sh[jl][0];
            float4 a1 = *(const float4*)&attn_sh[jl][4];
            U_loc[0] = fmaf(a0.x, va, U_loc[0]);
            U_loc[1] = fmaf(a0.y, va, U_loc[1]);
            U_loc[2] = fmaf(a0.z, va, U_loc[2]);
            U_loc[3] = fmaf(a0.w, va, U_loc[3]);
            U_loc[4] = fmaf(a1.x, va, U_loc[4]);
            U_loc[5] = fmaf(a1.y, va, U_loc[5]);
            U_loc[6] = fmaf(a1.z, va, U_loc[6]);
        }
        __syncthreads();
    }

    // ---- reduce S within block, then one global atomic per slot ----
    #pragma unroll
    for (int i = 0; i < NSL; i++) {
        float sv = S_loc[i];
        #pragma unroll
        for (int m = 16; m >= 1; m >>= 1) sv += __shfl_xor_sync(0xffffffffu, sv, m);
        if ((t & 31) == 0) atomicAdd(&S_sh[i], sv);
    }
    __syncthreads();
    if (t < NSL) atomicAdd(&g_S[b*NSL + t], S_sh[t]);
    #pragma unroll
    for (int i = 0; i < NSL; i++)
        atomicAdd(&g_U[(b*NSL + i)*DD + d], U_loc[i]);
}

// ============================================================
// Prep: slots0 = mu + sigma*noise; zero S/U; q0 = LN(slots0)@Wq.T+bq, *scale
// launched with 448 threads (= NSL*DD)
// ============================================================
__global__ void __launch_bounds__(448) prep_kernel(
    const float* __restrict__ noise, const float* __restrict__ mu,
    const float* __restrict__ sigma,
    const float* __restrict__ Wq, const float* __restrict__ bq,
    const float* __restrict__ gsl, const float* __restrict__ bsl)
{
    int b = blockIdx.x, t = threadIdx.x;
    __shared__ float sl[NSL*DD], sn[NSL*DD];
    __shared__ float mstat[NSL][2];
    if (t < NSL*DD) {
        int d = t & 63;
        float v = mu[d] + sigma[d]*noise[b*NSL*DD + t];
        sl[t] = v;
        g_slots[b*NSL*DD + t] = v;
        g_U[b*NSL*DD + t] = 0.f;
    }
    if (t < NSL) g_S[b*NSL + t] = 0.f;
    __syncthreads();
    if (t < NSL) {
        float s = 0.f, ss = 0.f;
        for (int j = 0; j < DD; j++) { float x = sl[t*DD + j]; s += x; ss += x*x; }
        float mean = s*(1.f/64.f), var = ss*(1.f/64.f) - mean*mean;
        mstat[t][0] = mean; mstat[t][1] = rsqrtf(var + 1e-5f);
    }
    __syncthreads();
    if (t < NSL*DD) {
        int i = t >> 6, d = t & 63;
        sn[t] = (sl[t] - mstat[i][0])*mstat[i][1]*gsl[d] + bsl[d];
    }
    __syncthreads();
    if (t < NSL*DD) {
        int i = t >> 6, d = t & 63;
        float q = bq[d];
        for (int j = 0; j < DD; j++) q = fmaf(sn[i*DD + j], Wq[d*DD + j], q);
        g_q[b*NSL*DD + t] = q * 0.125f;
    }
}

// ============================================================
// Finish v2: one block per (slot, batch); 256 thr = 8 warps.
// Warp-per-output, lane-split reduction dim, coalesced weight loads.
// ============================================================
__global__ void __launch_bounds__(256) finish_kernel(
    const float* __restrict__ W_ih, const float* __restrict__ W_hh,
    const float* __restrict__ b_ih, const float* __restrict__ b_hh,
    const float* __restrict__ mW1, const float* __restrict__ mb1,
    const float* __restrict__ mW2, const float* __restrict__ mb2,
    const float* __restrict__ gml, const float* __restrict__ bml,
    const float* __restrict__ Wq,  const float* __restrict__ bq,
    const float* __restrict__ gsl, const float* __restrict__ bsl,
    float* __restrict__ out, int is_last)
{
    int slot = blockIdx.x, b = blockIdx.y;
    int t = threadIdx.x, w = t >> 5, lane = t & 31;
    int sb = b*NSL + slot;

    __shared__ float u[64], p[64];
    __shared__ float xg[192], hg[192];
    __shared__ float snew[64], mn[64], hid[128], sfin[64], sq[64];
    __shared__ float stat[2];

    if (t < 64) {
        float S = g_S[sb];
        u[t] = g_U[sb*DD + t] / S;
        p[t] = g_slots[sb*DD + t];
    }
    __syncthreads();
    if (t < 64) g_U[sb*DD + t] = 0.f;   // re-arm for next iter/replay
    if (t == 0) g_S[sb] = 0.f;

    // ---- GRU gates: 192 (xa, ha) pairs, warp-per-output ----
    float u_lo = u[lane], u_hi = u[lane+32];
    float p_lo = p[lane], p_hi = p[lane+32];
    #pragma unroll 2
    for (int it = 0; it < 24; it++) {
        int gd = w + 8*it;
        const float* wi = W_ih + gd*DD;
        const float* wh = W_hh + gd*DD;
        float xa = u_lo*wi[lane] + u_hi*wi[lane+32];
        float ha = p_lo*wh[lane] + p_hi*wh[lane+32];
        xa = wred(xa); ha = wred(ha);
        if (lane == 0) { xg[gd] = xa + b_ih[gd]; hg[gd] = ha + b_hh[gd]; }
    }
    __syncthreads();

    if (t < 64) {
        float r = 1.f/(1.f + expf(-(xg[t]      + hg[t])));
        float z = 1.f/(1.f + expf(-(xg[64+t]   + hg[64+t])));
        float n = tanhf(xg[128+t] + r*hg[128+t]);
        snew[t] = (1.f - z)*n + z*p[t];
    }
    __syncthreads();

    // ---- LN (gml) on snew ----
    if (w == 0) {
        float a = snew[lane], c = snew[lane+32];
        float s  = wred(a + c);
        float ss = wred(a*a + c*c);
        if (lane == 0) {
            float mean = s*(1.f/64.f), var = ss*(1.f/64.f) - mean*mean;
            stat[0] = mean; stat[1] = rsqrtf(var + 1e-5f);
        }
    }
    __syncthreads();
    if (t < 64) mn[t] = (snew[t] - stat[0])*stat[1]*gml[t] + bml[t];
    __syncthreads();

    // ---- MLP hidden: 128 outputs ----
    float m_lo = mn[lane], m_hi = mn[lane+32];
    #pragma unroll 2
    for (int it = 0; it < 16; it++) {
        int hh = w + 8*it;
        const float* w1 = mW1 + hh*DD;
        float a = m_lo*w1[lane] + m_hi*w1[lane+32];
        a = wred(a);
        if (lane == 0) hid[hh] = fmaxf(a + mb1[hh], 0.f);
    }
    __syncthreads();

    // ---- MLP out + residual ----
    float h0 = hid[lane], h1 = hid[lane+32], h2 = hid[lane+64], h3 = hid[lane+96];
    #pragma unroll 2
    for (int it = 0; it < 8; it++) {
        int d = w + 8*it;
        const float* w2 = mW2 + d*HH;
        float a = h0*w2[lane] + h1*w2[lane+32] + h2*w2[lane+64] + h3*w2[lane+96];
        a = wred(a);
        if (lane == 0) {
            float vfin = snew[d] + a + mb2[d];
            sfin[d] = vfin;
            g_slots[sb*DD + d] = vfin;
            if (is_last) out[sb*DD + d] = vfin;
        }
    }
    __syncthreads();

    // ---- LN (gsl) on sfin ----
    if (w == 0) {
        float a = sfin[lane], c = sfin[lane+32];
        float s  = wred(a + c);
        float ss = wred(a*a + c*c);
        if (lane == 0) {
            float mean = s*(1.f/64.f), var = ss*(1.f/64.f) - mean*mean;
            stat[0] = mean; stat[1] = rsqrtf(var + 1e-5f);
        }
    }
    __syncthreads();
    if (t < 64) sq[t] = (sfin[t] - stat[0])*stat[1]*gsl[t] + bsl[t];
    __syncthreads();

    // ---- next q ----
    float s_lo = sq[lane], s_hi = sq[lane+32];
    #pragma unroll 2
    for (int it = 0; it < 8; it++) {
        int d = w + 8*it;
        const float* wq = Wq + d*DD;
        float a = s_lo*wq[lane] + s_hi*wq[lane+32];
        a = wred(a);
        if (lane == 0) g_q[sb*DD + d] = (a + bq[d]) * 0.125f;
    }
}

// ============================================================
extern "C" void kernel_launch(void* const* d_in, const int* in_sizes, int n_in,
                              void* d_out, int out_size)
{
    const float* inputs = (const float*)d_in[0];
    const float* noise  = (const float*)d_in[1];
    const float* mu     = (const float*)d_in[2];
    const float* sigma  = (const float*)d_in[3];
    const float* Wq     = (const float*)d_in[4];
    const float* bq     = (const float*)d_in[5];
    const float* Wk     = (const float*)d_in[6];
    const float* bk     = (const float*)d_in[7];
    const float* Wv     = (const float*)d_in[8];
    const float* bv     = (const float*)d_in[9];
    const float* W_ih   = (const float*)d_in[10];
    const float* W_hh   = (const float*)d_in[11];
    const float* b_ih   = (const float*)d_in[12];
    const float* b_hh   = (const float*)d_in[13];
    const float* mW1    = (const float*)d_in[14];
    const float* mb1    = (const float*)d_in[15];
    const float* mW2    = (const float*)d_in[16];
    const float* mb2    = (const float*)d_in[17];
    const float* gin    = (const float*)d_in[18];
    const float* bin    = (const float*)d_in[19];
    const float* gsl    = (const float*)d_in[20];
    const float* bsl    = (const float*)d_in[21];
    const float* gml    = (const float*)d_in[22];
    const float* bml    = (const float*)d_in[23];
    float* out = (float*)d_out;

    proj_kernel<<<2048, 256>>>(inputs, Wk, bk, Wv, bv, gin, bin);
    prep_kernel<<<BB, 448>>>(noise, mu, sigma, Wq, bq, gsl, bsl);
    for (int it = 0; it < 3; it++) {
        attn_kernel<<<dim3(16, BB), 256>>>();
        finish_kernel<<<dim3(NSL, BB), 256>>>(W_ih, W_hh, b_ih, b_hh, mW1, mb1, mW2, mb2,
                                              gml, bml, Wq, bq, gsl, bsl, out, (it == 2) ? 1 : 0);
    }
}

// round 10
// speedup vs baseline: 1.5141x; 1.0279x over previous
#include <cuda_runtime.h>

#define BB  32
#define NN  16384
#define DD  64
#define NSL 7
#define HH  128

// ---- scratch (device globals; no allocations allowed) ----
__device__ float g_k[(size_t)BB*NN*DD];   // stored TRANSPOSED: [b][d][n]
__device__ float g_v[(size_t)BB*NN*DD];   // row-major: [b][n][d]
__device__ float g_slots[BB*NSL*DD];
__device__ float g_q[BB*NSL*DD];
__device__ float g_U[BB*NSL*DD];
__device__ float g_S[BB*NSL];

__device__ __forceinline__ float wred(float v) {
    v += __shfl_xor_sync(0xffffffffu, v, 16);
    v += __shfl_xor_sync(0xffffffffu, v, 8);
    v += __shfl_xor_sync(0xffffffffu, v, 4);
    v += __shfl_xor_sync(0xffffffffu, v, 2);
    v += __shfl_xor_sync(0xffffffffu, v, 1);
    return v;
}

// ============================================================
// Projection: x = LN(inputs); k = x@Wk.T + bk (stored transposed);
// v = x@Wv.T + bv (row-major).
// grid 2048 blocks x 256 thr; each block: 256 rows (8 tiles of 32)
// ============================================================
__global__ void __launch_bounds__(256) proj_kernel(
    const float* __restrict__ inp,
    const float* __restrict__ Wk, const float* __restrict__ bk,
    const float* __restrict__ Wv, const float* __restrict__ bv,
    const float* __restrict__ gin, const float* __restrict__ bin)
{
    __shared__ float WkT[64*64];
    __shared__ float WvT[64*64];
    __shared__ __align__(16) float xT[64*36];
    __shared__ float gi[64], bi[64], bkv[128];

    int t = threadIdx.x;
    for (int e = t; e < 4096; e += 256) {
        int d = e >> 6, j = e & 63;
        WkT[j*64 + d] = Wk[e];
        WvT[j*64 + d] = Wv[e];
    }
    if (t < 64) { gi[t] = gin[t]; bi[t] = bin[t]; bkv[t] = bk[t]; bkv[64+t] = bv[t]; }
    __syncthreads();

    int w = t >> 5, lane = t & 31;
    int og = w & 3, rh = w >> 2;
    int isK = (og < 2);
    const float* WT = isK ? WkT : WvT;
    int col = lane + 32*(og & 1);
    float bias = bkv[(isK ? 0 : 64) + col];

    int r  = t >> 3;        // 0..31 row within tile (for LN phase)
    int j0 = t & 7;

    unsigned long long biasP;
    asm("mov.b64 %0, {%1, %1};" : "=l"(biasP) : "f"(bias));

    for (int tile = 0; tile < 8; tile++) {
        size_t row0 = (size_t)blockIdx.x*256 + (size_t)tile*32;

        // ---- LN: 8 threads per row, values kept in regs ----
        {
            const float* xrow = inp + (row0 + r)*DD;
            float xr[8];
            float s = 0.f, ss = 0.f;
            #pragma unroll
            for (int jj = 0; jj < 8; jj++) {
                float x = xrow[j0 + 8*jj];
                xr[jj] = x; s += x; ss += x*x;
            }
            #pragma unroll
            for (int m = 1; m <= 4; m <<= 1) {
                s  += __shfl_xor_sync(0xffffffffu, s,  m);
                ss += __shfl_xor_sync(0xffffffffu, ss, m);
            }
            float mean = s * (1.f/64.f);
            float var  = ss * (1.f/64.f) - mean*mean;
            float rstd = rsqrtf(var + 1e-5f);
            #pragma unroll
            for (int jj = 0; jj < 8; jj++) {
                int j = j0 + 8*jj;
                xT[j*36 + r] = (xr[jj] - mean)*rstd*gi[j] + bi[j];
            }
        }
        __syncthreads();

        // ---- GEMM: 16 rows x 1 col per lane, packed f32x2 ----
        unsigned long long accP[8];
        #pragma unroll
        for (int i = 0; i < 8; i++) accP[i] = biasP;
        #pragma unroll 8
        for (int j = 0; j < 64; j++) {
            float wv = WT[j*64 + col];
            unsigned long long wv2;
            asm("mov.b64 %0, {%1, %1};" : "=l"(wv2) : "f"(wv));
            const ulonglong2* xp = (const ulonglong2*)&xT[j*36 + rh*16];
            ulonglong2 xA = xp[0], xB = xp[1];
            asm("fma.rn.f32x2 %0, %1, %2, %0;" : "+l"(accP[0]) : "l"(wv2), "l"(xA.x));
            asm("fma.rn.f32x2 %0, %1, %2, %0;" : "+l"(accP[1]) : "l"(wv2), "l"(xA.y));
            asm("fma.rn.f32x2 %0, %1, %2, %0;" : "+l"(accP[2]) : "l"(wv2), "l"(xB.x));
            asm("fma.rn.f32x2 %0, %1, %2, %0;" : "+l"(accP[3]) : "l"(wv2), "l"(xB.y));
            const ulonglong2* xq = (const ulonglong2*)&xT[j*36 + rh*16 + 8];
            ulonglong2 xC = xq[0], xD = xq[1];
            asm("fma.rn.f32x2 %0, %1, %2, %0;" : "+l"(accP[4]) : "l"(wv2), "l"(xC.x));
            asm("fma.rn.f32x2 %0, %1, %2, %0;" : "+l"(accP[5]) : "l"(wv2), "l"(xC.y));
            asm("fma.rn.f32x2 %0, %1, %2, %0;" : "+l"(accP[6]) : "l"(wv2), "l"(xD.x));
            asm("fma.rn.f32x2 %0, %1, %2, %0;" : "+l"(accP[7]) : "l"(wv2), "l"(xD.y));
        }

        if (isK) {
            // k transposed store: [b][col][n], 16 consecutive n per thread
            int b = (int)(row0 >> 14);
            int n0 = (int)(row0 & 16383) + rh*16;
            float* dst = g_k + ((size_t)(b*64 + col))*NN + n0;
            #pragma unroll
            for (int i = 0; i < 4; i++) {
                float4 f;
                asm("mov.b64 {%0, %1}, %2;" : "=f"(f.x), "=f"(f.y) : "l"(accP[2*i]));
                asm("mov.b64 {%0, %1}, %2;" : "=f"(f.z), "=f"(f.w) : "l"(accP[2*i+1]));
                ((float4*)dst)[i] = f;
            }
        } else {
            float* dst = g_v + (row0 + (size_t)rh*16)*DD + col;
            #pragma unroll
            for (int i = 0; i < 8; i++) {
                float lo, hi;
                asm("mov.b64 {%0, %1}, %2;" : "=f"(lo), "=f"(hi) : "l"(accP[i]));
                dst[(size_t)(2*i)*DD]   = lo;
                dst[(size_t)(2*i+1)*DD] = hi;
            }
        }
        __syncthreads();
    }
}

// ============================================================
// Attention pass: grid (16 chunks, B), 256 thr, 1024 keys/block.
// Phase A: thread owns 4 consecutive keys; kT loads coalesced.
// Phase B: thread <-> (key-group g, d); smem pre-reduce over g
// before g_U atomics (4x fewer ATOMG).
// ============================================================
__global__ void __launch_bounds__(256) attn_kernel()
{
    int b = blockIdx.y;
    int t = threadIdx.x;
    __shared__ __align__(16) float q_sh[NSL*DD];
    __shared__ __align__(16) float attn_sh[1024][8];   // 32 KB
    __shared__ __align__(16) float red[4][64][8];      // 8 KB
    __shared__ float S_sh[NSL];

    for (int e = t; e < NSL*DD; e += 256) q_sh[e] = g_q[b*NSL*DD + e];
    if (t < NSL) S_sh[t] = 0.f;
    __syncthreads();

    int n0 = blockIdx.x * 1024;     // tile base within batch

    // ---- phase A: 4 keys per thread, coalesced kT loads ----
    float S_loc[NSL];
    #pragma unroll
    for (int i = 0; i < NSL; i++) S_loc[i] = 0.f;
    {
        const float* kb = g_k + ((size_t)b*64)*NN + n0 + 4*t;
        float acc[NSL][4];
        #pragma unroll
        for (int i = 0; i < NSL; i++)
            #pragma unroll
            for (int kk = 0; kk < 4; kk++) acc[i][kk] = 0.f;

        #pragma unroll 4
        for (int dc = 0; dc < 16; dc++) {
            float4 k0 = *(const float4*)(kb + (size_t)(4*dc+0)*NN);
            float4 k1 = *(const float4*)(kb + (size_t)(4*dc+1)*NN);
            float4 k2 = *(const float4*)(kb + (size_t)(4*dc+2)*NN);
            float4 k3 = *(const float4*)(kb + (size_t)(4*dc+3)*NN);
            #pragma unroll
            for (int i = 0; i < NSL; i++) {
                float4 q4 = *(const float4*)&q_sh[i*64 + 4*dc];
                acc[i][0] = fmaf(q4.x, k0.x, acc[i][0]);
                acc[i][1] = fmaf(q4.x, k0.y, acc[i][1]);
                acc[i][2] = fmaf(q4.x, k0.z, acc[i][2]);
                acc[i][3] = fmaf(q4.x, k0.w, acc[i][3]);
                acc[i][0] = fmaf(q4.y, k1.x, acc[i][0]);
                acc[i][1] = fmaf(q4.y, k1.y, acc[i][1]);
                acc[i][2] = fmaf(q4.y, k1.z, acc[i][2]);
                acc[i][3] = fmaf(q4.y, k1.w, acc[i][3]);
                acc[i][0] = fmaf(q4.z, k2.x, acc[i][0]);
                acc[i][1] = fmaf(q4.z, k2.y, acc[i][1]);
                acc[i][2] = fmaf(q4.z, k2.z, acc[i][2]);
                acc[i][3] = fmaf(q4.z, k2.w, acc[i][3]);
                acc[i][0] = fmaf(q4.w, k3.x, acc[i][0]);
                acc[i][1] = fmaf(q4.w, k3.y, acc[i][1]);
                acc[i][2] = fmaf(q4.w, k3.z, acc[i][2]);
                acc[i][3] = fmaf(q4.w, k3.w, acc[i][3]);
            }
        }
        // softmax over slots for each of the 4 keys
        #pragma unroll
        for (int kk = 0; kk < 4; kk++) {
            float mx = acc[0][kk];
            #pragma unroll
            for (int i = 1; i < NSL; i++) mx = fmaxf(mx, acc[i][kk]);
            float e[8]; float ssum = 0.f;
            #pragma unroll
            for (int i = 0; i < NSL; i++) { e[i] = __expf(acc[i][kk] - mx); ssum += e[i]; }
            float inv = __fdividef(1.f, ssum);
            #pragma unroll
            for (int i = 0; i < NSL; i++) {
                float p = fmaf(e[i], inv, 1e-8f);   // softmax + EPS
                e[i] = p; S_loc[i] += p;
            }
            e[7] = 0.f;
            int jl = 4*t + kk;
            *(float4*)&attn_sh[jl][0] = make_float4(e[0], e[1], e[2], e[3]);
            *(float4*)&attn_sh[jl][4] = make_float4(e[4], e[5], e[6], e[7]);
        }
    }
    __syncthreads();

    // ---- phase B: thread <-> (key-group, d); coalesced v reads ----
    int g = t >> 6, d = t & 63;
    float U_loc[NSL];
    #pragma unroll
    for (int i = 0; i < NSL; i++) U_loc[i] = 0.f;
    {
        const float* vp = g_v + ((size_t)b*NN + n0 + g*256)*DD + d;
        #pragma unroll 4
        for (int jj = 0; jj < 256; jj++) {
            float va = vp[(size_t)jj*DD];
            int jl = g*256 + jj;
            float4 a0 = *(const float4*)&attn_sh[jl][0];
            float4 a1 = *(const float4*)&attn_sh[jl][4];
            U_loc[0] = fmaf(a0.x, va, U_loc[0]);
            U_loc[1] = fmaf(a0.y, va, U_loc[1]);
            U_loc[2] = fmaf(a0.z, va, U_loc[2]);
            U_loc[3] = fmaf(a0.w, va, U_loc[3]);
            U_loc[4] = fmaf(a1.x, va, U_loc[4]);
            U_loc[5] = fmaf(a1.y, va, U_loc[5]);
            U_loc[6] = fmaf(a1.z, va, U_loc[6]);
        }
    }
    // pre-reduce U across g-groups in smem, then 1 atomic per (i,d)
    #pragma unroll
    for (int i = 0; i < NSL; i++) red[g][d][i] = U_loc[i];
    __syncthreads();
    if (g == 0) {
        #pragma unroll
        for (int i = 0; i < NSL; i++) {
            float s = red[0][d][i] + red[1][d][i] + red[2][d][i] + red[3][d][i];
            atomicAdd(&g_U[(b*NSL + i)*DD + d], s);
        }
    }

    // ---- reduce S within block, then one global atomic per slot ----
    #pragma unroll
    for (int i = 0; i < NSL; i++) {
        float sv = wred(S_loc[i]);
        if ((t & 31) == 0) atomicAdd(&S_sh[i], sv);
    }
    __syncthreads();
    if (t < NSL) atomicAdd(&g_S[b*NSL + t], S_sh[t]);
}

// ============================================================
// Prep: slots0 = mu + sigma*noise; zero S/U; q0 = LN(slots0)@Wq.T+bq, *scale
// launched with 448 threads (= NSL*DD)
// ============================================================
__global__ void __launch_bounds__(448) prep_kernel(
    const float* __restrict__ noise, const float* __restrict__ mu,
    const float* __restrict__ sigma,
    const float* __restrict__ Wq, const float* __restrict__ bq,
    const float* __restrict__ gsl, const float* __restrict__ bsl)
{
    int b = blockIdx.x, t = threadIdx.x;
    __shared__ float sl[NSL*DD], sn[NSL*DD];
    __shared__ float mstat[NSL][2];
    if (t < NSL*DD) {
        int d = t & 63;
        float v = mu[d] + sigma[d]*noise[b*NSL*DD + t];
        sl[t] = v;
        g_slots[b*NSL*DD + t] = v;
        g_U[b*NSL*DD + t] = 0.f;
    }
    if (t < NSL) g_S[b*NSL + t] = 0.f;
    __syncthreads();
    if (t < NSL) {
        float s = 0.f, ss = 0.f;
        for (int j = 0; j < DD; j++) { float x = sl[t*DD + j]; s += x; ss += x*x; }
        float mean = s*(1.f/64.f), var = ss*(1.f/64.f) - mean*mean;
        mstat[t][0] = mean; mstat[t][1] = rsqrtf(var + 1e-5f);
    }
    __syncthreads();
    if (t < NSL*DD) {
        int i = t >> 6, d = t & 63;
        sn[t] = (sl[t] - mstat[i][0])*mstat[i][1]*gsl[d] + bsl[d];
    }
    __syncthreads();
    if (t < NSL*DD) {
        int i = t >> 6, d = t & 63;
        float q = bq[d];
        for (int j = 0; j < DD; j++) q = fmaf(sn[i*DD + j], Wq[d*DD + j], q);
        g_q[b*NSL*DD + t] = q * 0.125f;
    }
}

// ============================================================
// Finish v3: one block per (slot, batch); 512 thr = 16 warps.
// Warp-per-output, full unroll (all weight LDGs issued up front).
// ============================================================
__global__ void __launch_bounds__(512) finish_kernel(
    const float* __restrict__ W_ih, const float* __restrict__ W_hh,
    const float* __restrict__ b_ih, const float* __restrict__ b_hh,
    const float* __restrict__ mW1, const float* __restrict__ mb1,
    const float* __restrict__ mW2, const float* __restrict__ mb2,
    const float* __restrict__ gml, const float* __restrict__ bml,
    const float* __restrict__ Wq,  const float* __restrict__ bq,
    const float* __restrict__ gsl, const float* __restrict__ bsl,
    float* __restrict__ out, int is_last)
{
    int slot = blockIdx.x, b = blockIdx.y;
    int t = threadIdx.x, w = t >> 5, lane = t & 31;
    int sb = b*NSL + slot;

    __shared__ float u[64], p[64];
    __shared__ float xg[192], hg[192];
    __shared__ float snew[64], mn[64], hid[128], sfin[64], sq[64];
    __shared__ float stat[2];

    if (t < 64) {
        float S = g_S[sb];
        u[t] = g_U[sb*DD + t] / S;
        p[t] = g_slots[sb*DD + t];
    }
    __syncthreads();
    if (t < 64) g_U[sb*DD + t] = 0.f;   // re-arm for next iter/replay
    if (t == 0) g_S[sb] = 0.f;

    // ---- GRU gates: 192 (xa, ha) pairs, warp-per-output, 12 its/warp ----
    float u_lo = u[lane], u_hi = u[lane+32];
    float p_lo = p[lane], p_hi = p[lane+32];
    #pragma unroll
    for (int it = 0; it < 12; it++) {
        int gd = w + 16*it;
        const float* wi = W_ih + gd*DD;
        const float* wh = W_hh + gd*DD;
        float xa = u_lo*wi[lane] + u_hi*wi[lane+32];
        float ha = p_lo*wh[lane] + p_hi*wh[lane+32];
        xa = wred(xa); ha = wred(ha);
        if (lane == 0) { xg[gd] = xa + b_ih[gd]; hg[gd] = ha + b_hh[gd]; }
    }
    __syncthreads();

    if (t < 64) {
        float r = 1.f/(1.f + expf(-(xg[t]      + hg[t])));
        float z = 1.f/(1.f + expf(-(xg[64+t]   + hg[64+t])));
        float n = tanhf(xg[128+t] + r*hg[128+t]);
        snew[t] = (1.f - z)*n + z*p[t];
    }
    __syncthreads();

    // ---- LN (gml) on snew ----
    if (w == 0) {
        float a = snew[lane], c = snew[lane+32];
        float s  = wred(a + c);
        float ss = wred(a*a + c*c);
        if (lane == 0) {
            float mean = s*(1.f/64.f), var = ss*(1.f/64.f) - mean*mean;
            stat[0] = mean; stat[1] = rsqrtf(var + 1e-5f);
        }
    }
    __syncthreads();
    if (t < 64) mn[t] = (snew[t] - stat[0])*stat[1]*gml[t] + bml[t];
    __syncthreads();

    // ---- MLP hidden: 128 outputs, 8 its/warp ----
    float m_lo = mn[lane], m_hi = mn[lane+32];
    #pragma unroll
    for (int it = 0; it < 8; it++) {
        int hh = w + 16*it;
        const float* w1 = mW1 + hh*DD;
        float a = m_lo*w1[lane] + m_hi*w1[lane+32];
        a = wred(a);
        if (lane == 0) hid[hh] = fmaxf(a + mb1[hh], 0.f);
    }
    __syncthreads();

    // ---- MLP out + residual: 64 outputs, 4 its/warp ----
    float h0 = hid[lane], h1 = hid[lane+32], h2 = hid[lane+64], h3 = hid[lane+96];
    #pragma unroll
    for (int it = 0; it < 4; it++) {
        int d = w + 16*it;
        const float* w2 = mW2 + d*HH;
        float a = h0*w2[lane] + h1*w2[lane+32] + h2*w2[lane+64] + h3*w2[lane+96];
        a = wred(a);
        if (lane == 0) {
            float vfin = snew[d] + a + mb2[d];
            sfin[d] = vfin;
            g_slots[sb*DD + d] = vfin;
            if (is_last) out[sb*DD + d] = vfin;
        }
    }
    __syncthreads();

    // ---- LN (gsl) on sfin ----
    if (w == 0) {
        float a = sfin[lane], c = sfin[lane+32];
        float s  = wred(a + c);
        float ss = wred(a*a + c*c);
        if (lane == 0) {
            float mean = s*(1.f/64.f), var = ss*(1.f/64.f) - mean*mean;
            stat[0] = mean; stat[1] = rsqrtf(var + 1e-5f);
        }
    }
    __syncthreads();
    if (t < 64) sq[t] = (sfin[t] - stat[0])*stat[1]*gsl[t] + bsl[t];
    __syncthreads();

    // ---- next q: 64 outputs, 4 its/warp ----
    float s_lo = sq[lane], s_hi = sq[lane+32];
    #pragma unroll
    for (int it = 0; it < 4; it++) {
        int d = w + 16*it;
        const float* wq = Wq + d*DD;
        float a = s_lo*wq[lane] + s_hi*wq[lane+32];
        a = wred(a);
        if (lane == 0) g_q[sb*DD + d] = (a + bq[d]) * 0.125f;
    }
}

// ============================================================
extern "C" void kernel_launch(void* const* d_in, const int* in_sizes, int n_in,
                              void* d_out, int out_size)
{
    const float* inputs = (const float*)d_in[0];
    const float* noise  = (const float*)d_in[1];
    const float* mu     = (const float*)d_in[2];
    const float* sigma  = (const float*)d_in[3];
    const float* Wq     = (const float*)d_in[4];
    const float* bq     = (const float*)d_in[5];
    const float* Wk     = (const float*)d_in[6];
    const float* bk     = (const float*)d_in[7];
    const float* Wv     = (const float*)d_in[8];
    const float* bv     = (const float*)d_in[9];
    const float* W_ih   = (const float*)d_in[10];
    const float* W_hh   = (const float*)d_in[11];
    const float* b_ih   = (const float*)d_in[12];
    const float* b_hh   = (const float*)d_in[13];
    const float* mW1    = (const float*)d_in[14];
    const float* mb1    = (const float*)d_in[15];
    const float* mW2    = (const float*)d_in[16];
    const float* mb2    = (const float*)d_in[17];
    const float* gin    = (const float*)d_in[18];
    const float* bin    = (const float*)d_in[19];
    const float* gsl    = (const float*)d_in[20];
    const float* bsl    = (const float*)d_in[21];
    const float* gml    = (const float*)d_in[22];
    const float* bml    = (const float*)d_in[23];
    float* out = (float*)d_out;

    proj_kernel<<<2048, 256>>>(inputs, Wk, bk, Wv, bv, gin, bin);
    prep_kernel<<<BB, 448>>>(noise, mu, sigma, Wq, bq, gsl, bsl);
    for (int it = 0; it < 3; it++) {
        attn_kernel<<<dim3(16, BB), 256>>>();
        finish_kernel<<<dim3(NSL, BB), 512>>>(W_ih, W_hh, b_ih, b_hh, mW1, mb1, mW2, mb2,
                                              gml, bml, Wq, bq, gsl, bsl, out, (it == 2) ? 1 : 0);
    }
}

// round 11
// speedup vs baseline: 1.6949x; 1.1194x over previous
#include <cuda_runtime.h>

#define BB  32
#define NN  16384
#define DD  64
#define NSL 7
#define HH  128

// ---- scratch (device globals; no allocations allowed) ----
__device__ float g_k[(size_t)BB*NN*DD];   // stored TRANSPOSED: [b][d][n]
__device__ float g_v[(size_t)BB*NN*DD];   // row-major: [b][n][d]
__device__ float g_slots[BB*NSL*DD];
__device__ float g_q[BB*NSL*DD];
__device__ float g_U[BB*NSL*DD];
__device__ float g_S[BB*NSL];

__device__ __forceinline__ float wred(float v) {
    v += __shfl_xor_sync(0xffffffffu, v, 16);
    v += __shfl_xor_sync(0xffffffffu, v, 8);
    v += __shfl_xor_sync(0xffffffffu, v, 4);
    v += __shfl_xor_sync(0xffffffffu, v, 2);
    v += __shfl_xor_sync(0xffffffffu, v, 1);
    return v;
}

// ============================================================
// Projection v3: x = LN(inputs); k = x@Wk.T + bk (transposed store);
// v = x@Wv.T + bv (row-major store).
// Block: 128 rows x 128 cols (k cols 0-63 | v cols 64-127), 256 thr.
// Thread: 8 rows x 8 cols register tile, f32x2 accumulators.
// x staged in smem with (j+rg)&63 swizzle -> conflict-free GEMM reads.
// Dynamic smem: xs 32KB + WT 33KB + params.
// ============================================================
__global__ void __launch_bounds__(256, 2) proj_kernel(
    const float* __restrict__ inp,
    const float* __restrict__ Wk, const float* __restrict__ bk,
    const float* __restrict__ Wv, const float* __restrict__ bv,
    const float* __restrict__ gin, const float* __restrict__ bin)
{
    extern __shared__ float sm[];
    float* xs      = sm;            // [128][64] swizzled: xs[r*64 + ((j + (r>>3))&63)]
    float* WT      = sm + 8192;     // [64][132]: WT[j*132 + c], c<64 -> Wk col, else Wv
    float* bias_sh = sm + 16640;    // [128]
    float* gi      = sm + 16768;    // [64]
    float* bi      = sm + 16832;    // [64]

    int t = threadIdx.x;

    // ---- stage WT (coalesced gmem reads over j) ----
    for (int e = t; e < 8192; e += 256) {
        int c = e >> 6, j = e & 63;
        float w = (c < 64) ? Wk[c*64 + j] : Wv[(c-64)*64 + j];
        WT[j*132 + c] = w;
    }
    if (t < 64) { gi[t] = gin[t]; bi[t] = bin[t]; bias_sh[t] = bk[t]; bias_sh[64+t] = bv[t]; }

    size_t row0 = (size_t)blockIdx.x * 128;
    int b  = (int)(row0 >> 14);
    int n0 = (int)(row0 & 16383);

    // ---- LN: warp per row, 16 passes; swizzled smem writes ----
    {
        int lrow = t >> 5;      // 0..7
        int lj   = t & 31;
        for (int pass = 0; pass < 16; pass++) {
            int r = pass*8 + lrow;
            const float* xrow = inp + (row0 + r)*DD;
            float a = xrow[lj], c2 = xrow[lj + 32];
            float s = a + c2, ss = a*a + c2*c2;
            s = wred(s); ss = wred(ss);
            float mean = s * (1.f/64.f);
            float var  = ss * (1.f/64.f) - mean*mean;
            float rstd = rsqrtf(var + 1e-5f);
            int sw = r >> 3;
            xs[r*64 + ((lj      + sw) & 63)] = (a  - mean)*rstd*gi[lj]      + bi[lj];
            xs[r*64 + ((lj + 32 + sw) & 63)] = (c2 - mean)*rstd*gi[lj + 32] + bi[lj + 32];
        }
    }
    __syncthreads();

    int cg = t >> 4, rg = t & 15;       // warp = (2 col-groups) x (16 row-groups)
    int c0 = cg * 8;                    // cols c0..c0+7 (c0<64: k, else v)
    int r0 = rg * 8;                    // local rows r0..r0+7

    // ---- init accumulators with bias ----
    unsigned long long acc[8][4];
    {
        unsigned long long bp[4];
        #pragma unroll
        for (int cp = 0; cp < 4; cp++)
            asm("mov.b64 %0, {%1, %2};" : "=l"(bp[cp])
                : "f"(bias_sh[c0 + 2*cp]), "f"(bias_sh[c0 + 2*cp + 1]));
        #pragma unroll
        for (int r = 0; r < 8; r++)
            #pragma unroll
            for (int cp = 0; cp < 4; cp++) acc[r][cp] = bp[cp];
    }

    // ---- GEMM mainloop: 64 j, 8x8 tile, f32x2 ----
    #pragma unroll 4
    for (int j = 0; j < 64; j++) {
        const ulonglong2* wp = (const ulonglong2*)&WT[j*132 + c0];
        ulonglong2 wA = wp[0], wB = wp[1];   // w2: wA.x wA.y wB.x wB.y
        #pragma unroll
        for (int r = 0; r < 8; r++) {
            float xv = xs[(r0 + r)*64 + ((j + rg) & 63)];
            unsigned long long x2;
            asm("mov.b64 %0, {%1, %1};" : "=l"(x2) : "f"(xv));
            asm("fma.rn.f32x2 %0, %1, %2, %0;" : "+l"(acc[r][0]) : "l"(x2), "l"(wA.x));
            asm("fma.rn.f32x2 %0, %1, %2, %0;" : "+l"(acc[r][1]) : "l"(x2), "l"(wA.y));
            asm("fma.rn.f32x2 %0, %1, %2, %0;" : "+l"(acc[r][2]) : "l"(x2), "l"(wB.x));
            asm("fma.rn.f32x2 %0, %1, %2, %0;" : "+l"(acc[r][3]) : "l"(x2), "l"(wB.y));
        }
    }

    // ---- unpack (register aliasing; movs mostly free) ----
    float af[8][8];
    #pragma unroll
    for (int r = 0; r < 8; r++)
        #pragma unroll
        for (int cp = 0; cp < 4; cp++)
            asm("mov.b64 {%0, %1}, %2;" : "=f"(af[r][2*cp]), "=f"(af[r][2*cp+1]) : "l"(acc[r][cp]));

    if (c0 < 64) {
        // ---- k transposed store: [b][col][n], 8 consecutive n per col ----
        #pragma unroll
        for (int cc = 0; cc < 8; cc++) {
            float* dst = g_k + ((size_t)(b*64 + c0 + cc))*NN + n0 + r0;
            ((float4*)dst)[0] = make_float4(af[0][cc], af[1][cc], af[2][cc], af[3][cc]);
            ((float4*)dst)[1] = make_float4(af[4][cc], af[5][cc], af[6][cc], af[7][cc]);
        }
    } else {
        // ---- v row-major store: 32B contiguous per row ----
        #pragma unroll
        for (int r = 0; r < 8; r++) {
            float* dst = g_v + (row0 + r0 + r)*DD + (c0 - 64);
            ((float4*)dst)[0] = make_float4(af[r][0], af[r][1], af[r][2], af[r][3]);
            ((float4*)dst)[1] = make_float4(af[r][4], af[r][5], af[r][6], af[r][7]);
        }
    }
}

// ============================================================
// Attention pass: grid (16 chunks, B), 256 thr, 1024 keys/block.
// Phase A: thread owns 4 consecutive keys; kT loads coalesced.
// Phase B: thread <-> (key-group g, d); smem pre-reduce over g
// before g_U atomics (4x fewer ATOMG).
// ============================================================
__global__ void __launch_bounds__(256) attn_kernel()
{
    int b = blockIdx.y;
    int t = threadIdx.x;
    __shared__ __align__(16) float q_sh[NSL*DD];
    __shared__ __align__(16) float attn_sh[1024][8];   // 32 KB
    __shared__ __align__(16) float red[4][64][8];      // 8 KB
    __shared__ float S_sh[NSL];

    for (int e = t; e < NSL*DD; e += 256) q_sh[e] = g_q[b*NSL*DD + e];
    if (t < NSL) S_sh[t] = 0.f;
    __syncthreads();

    int n0 = blockIdx.x * 1024;     // tile base within batch

    // ---- phase A: 4 keys per thread, coalesced kT loads ----
    float S_loc[NSL];
    #pragma unroll
    for (int i = 0; i < NSL; i++) S_loc[i] = 0.f;
    {
        const float* kb = g_k + ((size_t)b*64)*NN + n0 + 4*t;
        float acc[NSL][4];
        #pragma unroll
        for (int i = 0; i < NSL; i++)
            #pragma unroll
            for (int kk = 0; kk < 4; kk++) acc[i][kk] = 0.f;

        #pragma unroll 4
        for (int dc = 0; dc < 16; dc++) {
            float4 k0 = *(const float4*)(kb + (size_t)(4*dc+0)*NN);
            float4 k1 = *(const float4*)(kb + (size_t)(4*dc+1)*NN);
            float4 k2 = *(const float4*)(kb + (size_t)(4*dc+2)*NN);
            float4 k3 = *(const float4*)(kb + (size_t)(4*dc+3)*NN);
            #pragma unroll
            for (int i = 0; i < NSL; i++) {
                float4 q4 = *(const float4*)&q_sh[i*64 + 4*dc];
                acc[i][0] = fmaf(q4.x, k0.x, acc[i][0]);
                acc[i][1] = fmaf(q4.x, k0.y, acc[i][1]);
                acc[i][2] = fmaf(q4.x, k0.z, acc[i][2]);
                acc[i][3] = fmaf(q4.x, k0.w, acc[i][3]);
                acc[i][0] = fmaf(q4.y, k1.x, acc[i][0]);
                acc[i][1] = fmaf(q4.y, k1.y, acc[i][1]);
                acc[i][2] = fmaf(q4.y, k1.z, acc[i][2]);
                acc[i][3] = fmaf(q4.y, k1.w, acc[i][3]);
                acc[i][0] = fmaf(q4.z, k2.x, acc[i][0]);
                acc[i][1] = fmaf(q4.z, k2.y, acc[i][1]);
                acc[i][2] = fmaf(q4.z, k2.z, acc[i][2]);
                acc[i][3] = fmaf(q4.z, k2.w, acc[i][3]);
                acc[i][0] = fmaf(q4.w, k3.x, acc[i][0]);
                acc[i][1] = fmaf(q4.w, k3.y, acc[i][1]);
                acc[i][2] = fmaf(q4.w, k3.z, acc[i][2]);
                acc[i][3] = fmaf(q4.w, k3.w, acc[i][3]);
            }
        }
        // softmax over slots for each of the 4 keys
        #pragma unroll
        for (int kk = 0; kk < 4; kk++) {
            float mx = acc[0][kk];
            #pragma unroll
            for (int i = 1; i < NSL; i++) mx = fmaxf(mx, acc[i][kk]);
            float e[8]; float ssum = 0.f;
            #pragma unroll
            for (int i = 0; i < NSL; i++) { e[i] = __expf(acc[i][kk] - mx); ssum += e[i]; }
            float inv = __fdividef(1.f, ssum);
            #pragma unroll
            for (int i = 0; i < NSL; i++) {
                float p = fmaf(e[i], inv, 1e-8f);   // softmax + EPS
                e[i] = p; S_loc[i] += p;
            }
            e[7] = 0.f;
            int jl = 4*t + kk;
            *(float4*)&attn_sh[jl][0] = make_float4(e[0], e[1], e[2], e[3]);
            *(float4*)&attn_sh[jl][4] = make_float4(e[4], e[5], e[6], e[7]);
        }
    }
    __syncthreads();

    // ---- phase B: thread <-> (key-group, d); coalesced v reads ----
    int g = t >> 6, d = t & 63;
    float U_loc[NSL];
    #pragma unroll
    for (int i = 0; i < NSL; i++) U_loc[i] = 0.f;
    {
        const float* vp = g_v + ((size_t)b*NN + n0 + g*256)*DD + d;
        #pragma unroll 4
        for (int jj = 0; jj < 256; jj++) {
            float va = vp[(size_t)jj*DD];
            int jl = g*256 + jj;
            float4 a0 = *(const float4*)&attn_sh[jl][0];
            float4 a1 = *(const float4*)&attn_sh[jl][4];
            U_loc[0] = fmaf(a0.x, va, U_loc[0]);
            U_loc[1] = fmaf(a0.y, va, U_loc[1]);
            U_loc[2] = fmaf(a0.z, va, U_loc[2]);
            U_loc[3] = fmaf(a0.w, va, U_loc[3]);
            U_loc[4] = fmaf(a1.x, va, U_loc[4]);
            U_loc[5] = fmaf(a1.y, va, U_loc[5]);
            U_loc[6] = fmaf(a1.z, va, U_loc[6]);
        }
    }
    // pre-reduce U across g-groups in smem, then 1 atomic per (i,d)
    #pragma unroll
    for (int i = 0; i < NSL; i++) red[g][d][i] = U_loc[i];
    __syncthreads();
    if (g == 0) {
        #pragma unroll
        for (int i = 0; i < NSL; i++) {
            float s = red[0][d][i] + red[1][d][i] + red[2][d][i] + red[3][d][i];
            atomicAdd(&g_U[(b*NSL + i)*DD + d], s);
        }
    }

    // ---- reduce S within block, then one global atomic per slot ----
    #pragma unroll
    for (int i = 0; i < NSL; i++) {
        float sv = wred(S_loc[i]);
        if ((t & 31) == 0) atomicAdd(&S_sh[i], sv);
    }
    __syncthreads();
    if (t < NSL) atomicAdd(&g_S[b*NSL + t], S_sh[t]);
}

// ============================================================
// Prep: slots0 = mu + sigma*noise; zero S/U; q0 = LN(slots0)@Wq.T+bq, *scale
// launched with 448 threads (= NSL*DD)
// ============================================================
__global__ void __launch_bounds__(448) prep_kernel(
    const float* __restrict__ noise, const float* __restrict__ mu,
    const float* __restrict__ sigma,
    const float* __restrict__ Wq, const float* __restrict__ bq,
    const float* __restrict__ gsl, const float* __restrict__ bsl)
{
    int b = blockIdx.x, t = threadIdx.x;
    __shared__ float sl[NSL*DD], sn[NSL*DD];
    __shared__ float mstat[NSL][2];
    if (t < NSL*DD) {
        int d = t & 63;
        float v = mu[d] + sigma[d]*noise[b*NSL*DD + t];
        sl[t] = v;
        g_slots[b*NSL*DD + t] = v;
        g_U[b*NSL*DD + t] = 0.f;
    }
    if (t < NSL) g_S[b*NSL + t] = 0.f;
    __syncthreads();
    if (t < NSL) {
        float s = 0.f, ss = 0.f;
        for (int j = 0; j < DD; j++) { float x = sl[t*DD + j]; s += x; ss += x*x; }
        float mean = s*(1.f/64.f), var = ss*(1.f/64.f) - mean*mean;
        mstat[t][0] = mean; mstat[t][1] = rsqrtf(var + 1e-5f);
    }
    __syncthreads();
    if (t < NSL*DD) {
        int i = t >> 6, d = t & 63;
        sn[t] = (sl[t] - mstat[i][0])*mstat[i][1]*gsl[d] + bsl[d];
    }
    __syncthreads();
    if (t < NSL*DD) {
        int i = t >> 6, d = t & 63;
        float q = bq[d];
        for (int j = 0; j < DD; j++) q = fmaf(sn[i*DD + j], Wq[d*DD + j], q);
        g_q[b*NSL*DD + t] = q * 0.125f;
    }
}

// ============================================================
// Finish v3: one block per (slot, batch); 512 thr = 16 warps.
// Warp-per-output, full unroll (all weight LDGs issued up front).
// ============================================================
__global__ void __launch_bounds__(512) finish_kernel(
    const float* __restrict__ W_ih, const float* __restrict__ W_hh,
    const float* __restrict__ b_ih, const float* __restrict__ b_hh,
    const float* __restrict__ mW1, const float* __restrict__ mb1,
    const float* __restrict__ mW2, const float* __restrict__ mb2,
    const float* __restrict__ gml, const float* __restrict__ bml,
    const float* __restrict__ Wq,  const float* __restrict__ bq,
    const float* __restrict__ gsl, const float* __restrict__ bsl,
    float* __restrict__ out, int is_last)
{
    int slot = blockIdx.x, b = blockIdx.y;
    int t = threadIdx.x, w = t >> 5, lane = t & 31;
    int sb = b*NSL + slot;

    __shared__ float u[64], p[64];
    __shared__ float xg[192], hg[192];
    __shared__ float snew[64], mn[64], hid[128], sfin[64], sq[64];
    __shared__ float stat[2];

    if (t < 64) {
        float S = g_S[sb];
        u[t] = g_U[sb*DD + t] / S;
        p[t] = g_slots[sb*DD + t];
    }
    __syncthreads();
    if (t < 64) g_U[sb*DD + t] = 0.f;   // re-arm for next iter/replay
    if (t == 0) g_S[sb] = 0.f;

    // ---- GRU gates: 192 (xa, ha) pairs, warp-per-output, 12 its/warp ----
    float u_lo = u[lane], u_hi = u[lane+32];
    float p_lo = p[lane], p_hi = p[lane+32];
    #pragma unroll
    for (int it = 0; it < 12; it++) {
        int gd = w + 16*it;
        const float* wi = W_ih + gd*DD;
        const float* wh = W_hh + gd*DD;
        float xa = u_lo*wi[lane] + u_hi*wi[lane+32];
        float ha = p_lo*wh[lane] + p_hi*wh[lane+32];
        xa = wred(xa); ha = wred(ha);
        if (lane == 0) { xg[gd] = xa + b_ih[gd]; hg[gd] = ha + b_hh[gd]; }
    }
    __syncthreads();

    if (t < 64) {
        float r = 1.f/(1.f + expf(-(xg[t]      + hg[t])));
        float z = 1.f/(1.f + expf(-(xg[64+t]   + hg[64+t])));
        float n = tanhf(xg[128+t] + r*hg[128+t]);
        snew[t] = (1.f - z)*n + z*p[t];
    }
    __syncthreads();

    // ---- LN (gml) on snew ----
    if (w == 0) {
        float a = snew[lane], c = snew[lane+32];
        float s  = wred(a + c);
        float ss = wred(a*a + c*c);
        if (lane == 0) {
            float mean = s*(1.f/64.f), var = ss*(1.f/64.f) - mean*mean;
            stat[0] = mean; stat[1] = rsqrtf(var + 1e-5f);
        }
    }
    __syncthreads();
    if (t < 64) mn[t] = (snew[t] - stat[0])*stat[1]*gml[t] + bml[t];
    __syncthreads();

    // ---- MLP hidden: 128 outputs, 8 its/warp ----
    float m_lo = mn[lane], m_hi = mn[lane+32];
    #pragma unroll
    for (int it = 0; it < 8; it++) {
        int hh = w + 16*it;
        const float* w1 = mW1 + hh*DD;
        float a = m_lo*w1[lane] + m_hi*w1[lane+32];
        a = wred(a);
        if (lane == 0) hid[hh] = fmaxf(a + mb1[hh], 0.f);
    }
    __syncthreads();

    // ---- MLP out + residual: 64 outputs, 4 its/warp ----
    float h0 = hid[lane], h1 = hid[lane+32], h2 = hid[lane+64], h3 = hid[lane+96];
    #pragma unroll
    for (int it = 0; it < 4; it++) {
        int d = w + 16*it;
        const float* w2 = mW2 + d*HH;
        float a = h0*w2[lane] + h1*w2[lane+32] + h2*w2[lane+64] + h3*w2[lane+96];
        a = wred(a);
        if (lane == 0) {
            float vfin = snew[d] + a + mb2[d];
            sfin[d] = vfin;
            g_slots[sb*DD + d] = vfin;
            if (is_last) out[sb*DD + d] = vfin;
        }
    }
    __syncthreads();

    // ---- LN (gsl) on sfin ----
    if (w == 0) {
        float a = sfin[lane], c = sfin[lane+32];
        float s  = wred(a + c);
        float ss = wred(a*a + c*c);
        if (lane == 0) {
            float mean = s*(1.f/64.f), var = ss*(1.f/64.f) - mean*mean;
            stat[0] = mean; stat[1] = rsqrtf(var + 1e-5f);
        }
    }
    __syncthreads();
    if (t < 64) sq[t] = (sfin[t] - stat[0])*stat[1]*gsl[t] + bsl[t];
    __syncthreads();

    // ---- next q: 64 outputs, 4 its/warp ----
    float s_lo = sq[lane], s_hi = sq[lane+32];
    #pragma unroll
    for (int it = 0; it < 4; it++) {
        int d = w + 16*it;
        const float* wq = Wq + d*DD;
        float a = s_lo*wq[lane] + s_hi*wq[lane+32];
        a = wred(a);
        if (lane == 0) g_q[sb*DD + d] = (a + bq[d]) * 0.125f;
    }
}

// ============================================================
extern "C" void kernel_launch(void* const* d_in, const int* in_sizes, int n_in,
                              void* d_out, int out_size)
{
    const float* inputs = (const float*)d_in[0];
    const float* noise  = (const float*)d_in[1];
    const float* mu     = (const float*)d_in[2];
    const float* sigma  = (const float*)d_in[3];
    const float* Wq     = (const float*)d_in[4];
    const float* bq     = (const float*)d_in[5];
    const float* Wk     = (const float*)d_in[6];
    const float* bk     = (const float*)d_in[7];
    const float* Wv     = (const float*)d_in[8];
    const float* bv     = (const float*)d_in[9];
    const float* W_ih   = (const float*)d_in[10];
    const float* W_hh   = (const float*)d_in[11];
    const float* b_ih   = (const float*)d_in[12];
    const float* b_hh   = (const float*)d_in[13];
    const float* mW1    = (const float*)d_in[14];
    const float* mb1    = (const float*)d_in[15];
    const float* mW2    = (const float*)d_in[16];
    const float* mb2    = (const float*)d_in[17];
    const float* gin    = (const float*)d_in[18];
    const float* bin    = (const float*)d_in[19];
    const float* gsl    = (const float*)d_in[20];
    const float* bsl    = (const float*)d_in[21];
    const float* gml    = (const float*)d_in[22];
    const float* bml    = (const float*)d_in[23];
    float* out = (float*)d_out;

    const int PROJ_SMEM = 16960 * 4;   // xs 8192 + WT 8448 + bias 128 + gi/bi 128 floats
    static int attr_set = 0;
    if (!attr_set) {
        cudaFuncSetAttribute(proj_kernel, cudaFuncAttributeMaxDynamicSharedMemorySize, PROJ_SMEM);
        attr_set = 1;
    }

    proj_kernel<<<4096, 256, PROJ_SMEM>>>(inputs, Wk, bk, Wv, bv, gin, bin);
    prep_kernel<<<BB, 448>>>(noise, mu, sigma, Wq, bq, gsl, bsl);
    for (int it = 0; it < 3; it++) {
        attn_kernel<<<dim3(16, BB), 256>>>();
        finish_kernel<<<dim3(NSL, BB), 512>>>(W_ih, W_hh, b_ih, b_hh, mW1, mb1, mW2, mb2,
                                              gml, bml, Wq, bq, gsl, bsl, out, (it == 2) ? 1 : 0);
    }
}

// round 12
// speedup vs baseline: 2.0091x; 1.1854x over previous
#include <cuda_runtime.h>

#define BB  32
#define NN  16384
#define DD  64
#define NSL 7
#define HH  128

// ---- scratch (device globals; no allocations allowed) ----
__device__ float g_k[(size_t)BB*NN*DD];   // stored TRANSPOSED: [b][d][n]
__device__ float g_v[(size_t)BB*NN*DD];   // row-major: [b][n][d]
__device__ float g_slots[BB*NSL*DD];
__device__ float g_q[BB*NSL*DD];
__device__ float g_U[BB*NSL*DD];
__device__ float g_S[BB*NSL];

__device__ __forceinline__ float wred(float v) {
    v += __shfl_xor_sync(0xffffffffu, v, 16);
    v += __shfl_xor_sync(0xffffffffu, v, 8);
    v += __shfl_xor_sync(0xffffffffu, v, 4);
    v += __shfl_xor_sync(0xffffffffu, v, 2);
    v += __shfl_xor_sync(0xffffffffu, v, 1);
    return v;
}

// dummy: shifts ncu capture index so launch #5 is attn_kernel
__global__ void dummy_kernel() {}

// ============================================================
// Projection v3 (unchanged from R11)
// ============================================================
__global__ void __launch_bounds__(256, 2) proj_kernel(
    const float* __restrict__ inp,
    const float* __restrict__ Wk, const float* __restrict__ bk,
    const float* __restrict__ Wv, const float* __restrict__ bv,
    const float* __restrict__ gin, const float* __restrict__ bin)
{
    extern __shared__ float sm[];
    float* xs      = sm;            // [128][64] swizzled: xs[r*64 + ((j + (r>>3))&63)]
    float* WT      = sm + 8192;     // [64][132]
    float* bias_sh = sm + 16640;    // [128]
    float* gi      = sm + 16768;    // [64]
    float* bi      = sm + 16832;    // [64]

    int t = threadIdx.x;

    for (int e = t; e < 8192; e += 256) {
        int c = e >> 6, j = e & 63;
        float w = (c < 64) ? Wk[c*64 + j] : Wv[(c-64)*64 + j];
        WT[j*132 + c] = w;
    }
    if (t < 64) { gi[t] = gin[t]; bi[t] = bin[t]; bias_sh[t] = bk[t]; bias_sh[64+t] = bv[t]; }

    size_t row0 = (size_t)blockIdx.x * 128;
    int b  = (int)(row0 >> 14);
    int n0 = (int)(row0 & 16383);

    {
        int lrow = t >> 5;
        int lj   = t & 31;
        for (int pass = 0; pass < 16; pass++) {
            int r = pass*8 + lrow;
            const float* xrow = inp + (row0 + r)*DD;
            float a = xrow[lj], c2 = xrow[lj + 32];
            float s = a + c2, ss = a*a + c2*c2;
            s = wred(s); ss = wred(ss);
            float mean = s * (1.f/64.f);
            float var  = ss * (1.f/64.f) - mean*mean;
            float rstd = rsqrtf(var + 1e-5f);
            int sw = r >> 3;
            xs[r*64 + ((lj      + sw) & 63)] = (a  - mean)*rstd*gi[lj]      + bi[lj];
            xs[r*64 + ((lj + 32 + sw) & 63)] = (c2 - mean)*rstd*gi[lj + 32] + bi[lj + 32];
        }
    }
    __syncthreads();

    int cg = t >> 4, rg = t & 15;
    int c0 = cg * 8;
    int r0 = rg * 8;

    unsigned long long acc[8][4];
    {
        unsigned long long bp[4];
        #pragma unroll
        for (int cp = 0; cp < 4; cp++)
            asm("mov.b64 %0, {%1, %2};" : "=l"(bp[cp])
                : "f"(bias_sh[c0 + 2*cp]), "f"(bias_sh[c0 + 2*cp + 1]));
        #pragma unroll
        for (int r = 0; r < 8; r++)
            #pragma unroll
            for (int cp = 0; cp < 4; cp++) acc[r][cp] = bp[cp];
    }

    #pragma unroll 4
    for (int j = 0; j < 64; j++) {
        const ulonglong2* wp = (const ulonglong2*)&WT[j*132 + c0];
        ulonglong2 wA = wp[0], wB = wp[1];
        #pragma unroll
        for (int r = 0; r < 8; r++) {
            float xv = xs[(r0 + r)*64 + ((j + rg) & 63)];
            unsigned long long x2;
            asm("mov.b64 %0, {%1, %1};" : "=l"(x2) : "f"(xv));
            asm("fma.rn.f32x2 %0, %1, %2, %0;" : "+l"(acc[r][0]) : "l"(x2), "l"(wA.x));
            asm("fma.rn.f32x2 %0, %1, %2, %0;" : "+l"(acc[r][1]) : "l"(x2), "l"(wA.y));
            asm("fma.rn.f32x2 %0, %1, %2, %0;" : "+l"(acc[r][2]) : "l"(x2), "l"(wB.x));
            asm("fma.rn.f32x2 %0, %1, %2, %0;" : "+l"(acc[r][3]) : "l"(x2), "l"(wB.y));
        }
    }

    float af[8][8];
    #pragma unroll
    for (int r = 0; r < 8; r++)
        #pragma unroll
        for (int cp = 0; cp < 4; cp++)
            asm("mov.b64 {%0, %1}, %2;" : "=f"(af[r][2*cp]), "=f"(af[r][2*cp+1]) : "l"(acc[r][cp]));

    if (c0 < 64) {
        #pragma unroll
        for (int cc = 0; cc < 8; cc++) {
            float* dst = g_k + ((size_t)(b*64 + c0 + cc))*NN + n0 + r0;
            ((float4*)dst)[0] = make_float4(af[0][cc], af[1][cc], af[2][cc], af[3][cc]);
            ((float4*)dst)[1] = make_float4(af[4][cc], af[5][cc], af[6][cc], af[7][cc]);
        }
    } else {
        #pragma unroll
        for (int r = 0; r < 8; r++) {
            float* dst = g_v + (row0 + r0 + r)*DD + (c0 - 64);
            ((float4*)dst)[0] = make_float4(af[r][0], af[r][1], af[r][2], af[r][3]);
            ((float4*)dst)[1] = make_float4(af[r][4], af[r][5], af[r][6], af[r][7]);
        }
    }
}

// ============================================================
// Attention v2: grid (32 chunks, B), 256 thr, 512 keys/block.
// Phase A: 2 keys/thread, coalesced float2 kT loads.
// Phase B: 16 key-groups x 16 d-quads; LDG.128 v loads; float4 U.
// smem pre-reduce over 16 groups before g_U atomics.
// ============================================================
__global__ void __launch_bounds__(256) attn_kernel()
{
    int b = blockIdx.y;
    int t = threadIdx.x;
    __shared__ __align__(16) float q_sh[NSL*DD];
    __shared__ __align__(16) float attn_sh[512][8];     // 16 KB
    __shared__ __align__(16) float4 red4[16][16][NSL];  // 28 KB
    __shared__ float S_sh[NSL];

    for (int e = t; e < NSL*DD; e += 256) q_sh[e] = g_q[b*NSL*DD + e];
    if (t < NSL) S_sh[t] = 0.f;
    __syncthreads();

    int n0 = blockIdx.x * 512;     // tile base within batch

    // ---- phase A: 2 keys per thread ----
    float S_loc[NSL];
    #pragma unroll
    for (int i = 0; i < NSL; i++) S_loc[i] = 0.f;
    {
        const float* kb = g_k + ((size_t)b*64)*NN + n0 + 2*t;
        float acc[NSL][2];
        #pragma unroll
        for (int i = 0; i < NSL; i++) { acc[i][0] = 0.f; acc[i][1] = 0.f; }

        #pragma unroll 4
        for (int dc = 0; dc < 16; dc++) {
            float2 k0 = *(const float2*)(kb + (size_t)(4*dc+0)*NN);
            float2 k1 = *(const float2*)(kb + (size_t)(4*dc+1)*NN);
            float2 k2 = *(const float2*)(kb + (size_t)(4*dc+2)*NN);
            float2 k3 = *(const float2*)(kb + (size_t)(4*dc+3)*NN);
            #pragma unroll
            for (int i = 0; i < NSL; i++) {
                float4 q4 = *(const float4*)&q_sh[i*64 + 4*dc];
                acc[i][0] = fmaf(q4.x, k0.x, acc[i][0]);
                acc[i][1] = fmaf(q4.x, k0.y, acc[i][1]);
                acc[i][0] = fmaf(q4.y, k1.x, acc[i][0]);
                acc[i][1] = fmaf(q4.y, k1.y, acc[i][1]);
                acc[i][0] = fmaf(q4.z, k2.x, acc[i][0]);
                acc[i][1] = fmaf(q4.z, k2.y, acc[i][1]);
                acc[i][0] = fmaf(q4.w, k3.x, acc[i][0]);
                acc[i][1] = fmaf(q4.w, k3.y, acc[i][1]);
            }
        }
        #pragma unroll
        for (int kk = 0; kk < 2; kk++) {
            float mx = acc[0][kk];
            #pragma unroll
            for (int i = 1; i < NSL; i++) mx = fmaxf(mx, acc[i][kk]);
            float e[8]; float ssum = 0.f;
            #pragma unroll
            for (int i = 0; i < NSL; i++) { e[i] = __expf(acc[i][kk] - mx); ssum += e[i]; }
            float inv = __fdividef(1.f, ssum);
            #pragma unroll
            for (int i = 0; i < NSL; i++) {
                float p = fmaf(e[i], inv, 1e-8f);   // softmax + EPS
                e[i] = p; S_loc[i] += p;
            }
            e[7] = 0.f;
            int jl = 2*t + kk;
            *(float4*)&attn_sh[jl][0] = make_float4(e[0], e[1], e[2], e[3]);
            *(float4*)&attn_sh[jl][4] = make_float4(e[4], e[5], e[6], e[7]);
        }
    }
    __syncthreads();

    // ---- phase B: 16 key-groups (32 keys each) x 16 d-quads ----
    int g = t >> 4, dq = t & 15;
    float4 U[NSL];
    #pragma unroll
    for (int i = 0; i < NSL; i++) U[i] = make_float4(0.f, 0.f, 0.f, 0.f);
    {
        const float4* vp = (const float4*)(g_v + ((size_t)b*NN + n0 + g*32)*DD) + dq;
        #pragma unroll 4
        for (int jj = 0; jj < 32; jj++) {
            float4 v4 = vp[(size_t)jj*16];
            int jl = g*32 + jj;
            float4 a0 = *(const float4*)&attn_sh[jl][0];
            float4 a1 = *(const float4*)&attn_sh[jl][4];
            U[0].x = fmaf(a0.x, v4.x, U[0].x); U[0].y = fmaf(a0.x, v4.y, U[0].y);
            U[0].z = fmaf(a0.x, v4.z, U[0].z); U[0].w = fmaf(a0.x, v4.w, U[0].w);
            U[1].x = fmaf(a0.y, v4.x, U[1].x); U[1].y = fmaf(a0.y, v4.y, U[1].y);
            U[1].z = fmaf(a0.y, v4.z, U[1].z); U[1].w = fmaf(a0.y, v4.w, U[1].w);
            U[2].x = fmaf(a0.z, v4.x, U[2].x); U[2].y = fmaf(a0.z, v4.y, U[2].y);
            U[2].z = fmaf(a0.z, v4.z, U[2].z); U[2].w = fmaf(a0.z, v4.w, U[2].w);
            U[3].x = fmaf(a0.w, v4.x, U[3].x); U[3].y = fmaf(a0.w, v4.y, U[3].y);
            U[3].z = fmaf(a0.w, v4.z, U[3].z); U[3].w = fmaf(a0.w, v4.w, U[3].w);
            U[4].x = fmaf(a1.x, v4.x, U[4].x); U[4].y = fmaf(a1.x, v4.y, U[4].y);
            U[4].z = fmaf(a1.x, v4.z, U[4].z); U[4].w = fmaf(a1.x, v4.w, U[4].w);
            U[5].x = fmaf(a1.y, v4.x, U[5].x); U[5].y = fmaf(a1.y, v4.y, U[5].y);
            U[5].z = fmaf(a1.y, v4.z, U[5].z); U[5].w = fmaf(a1.y, v4.w, U[5].w);
            U[6].x = fmaf(a1.z, v4.x, U[6].x); U[6].y = fmaf(a1.z, v4.y, U[6].y);
            U[6].z = fmaf(a1.z, v4.z, U[6].z); U[6].w = fmaf(a1.z, v4.w, U[6].w);
        }
    }
    #pragma unroll
    for (int i = 0; i < NSL; i++) red4[g][dq][i] = U[i];
    __syncthreads();

    // final reduce over 16 groups; 448 (i,d) outputs over 256 threads
    for (int e = t; e < NSL*DD; e += 256) {
        int i = e >> 6, d = e & 63;
        int dq2 = d >> 2, c = d & 3;
        const float* base = (const float*)&red4[0][dq2][i] + c;
        float s = 0.f;
        #pragma unroll
        for (int gg = 0; gg < 16; gg++)
            s += base[gg*16*NSL*4];   // stride: one g step = 16*NSL float4s
        atomicAdd(&g_U[(b*NSL + i)*DD + d], s);
    }

    // ---- reduce S within block, then one global atomic per slot ----
    #pragma unroll
    for (int i = 0; i < NSL; i++) {
        float sv = wred(S_loc[i]);
        if ((t & 31) == 0) atomicAdd(&S_sh[i], sv);
    }
    __syncthreads();
    if (t < NSL) atomicAdd(&g_S[b*NSL + t], S_sh[t]);
}

// ============================================================
// Prep (unchanged)
// ============================================================
__global__ void __launch_bounds__(448) prep_kernel(
    const float* __restrict__ noise, const float* __restrict__ mu,
    const float* __restrict__ sigma,
    const float* __restrict__ Wq, const float* __restrict__ bq,
    const float* __restrict__ gsl, const float* __restrict__ bsl)
{
    int b = blockIdx.x, t = threadIdx.x;
    __shared__ float sl[NSL*DD], sn[NSL*DD];
    __shared__ float mstat[NSL][2];
    if (t < NSL*DD) {
        int d = t & 63;
        float v = mu[d] + sigma[d]*noise[b*NSL*DD + t];
        sl[t] = v;
        g_slots[b*NSL*DD + t] = v;
        g_U[b*NSL*DD + t] = 0.f;
    }
    if (t < NSL) g_S[b*NSL + t] = 0.f;
    __syncthreads();
    if (t < NSL) {
        float s = 0.f, ss = 0.f;
        for (int j = 0; j < DD; j++) { float x = sl[t*DD + j]; s += x; ss += x*x; }
        float mean = s*(1.f/64.f), var = ss*(1.f/64.f) - mean*mean;
        mstat[t][0] = mean; mstat[t][1] = rsqrtf(var + 1e-5f);
    }
    __syncthreads();
    if (t < NSL*DD) {
        int i = t >> 6, d = t & 63;
        sn[t] = (sl[t] - mstat[i][0])*mstat[i][1]*gsl[d] + bsl[d];
    }
    __syncthreads();
    if (t < NSL*DD) {
        int i = t >> 6, d = t & 63;
        float q = bq[d];
        for (int j = 0; j < DD; j++) q = fmaf(sn[i*DD + j], Wq[d*DD + j], q);
        g_q[b*NSL*DD + t] = q * 0.125f;
    }
}

// ============================================================
// Finish v3 (unchanged)
// ============================================================
__global__ void __launch_bounds__(512) finish_kernel(
    const float* __restrict__ W_ih, const float* __restrict__ W_hh,
    const float* __restrict__ b_ih, const float* __restrict__ b_hh,
    const float* __restrict__ mW1, const float* __restrict__ mb1,
    const float* __restrict__ mW2, const float* __restrict__ mb2,
    const float* __restrict__ gml, const float* __restrict__ bml,
    const float* __restrict__ Wq,  const float* __restrict__ bq,
    const float* __restrict__ gsl, const float* __restrict__ bsl,
    float* __restrict__ out, int is_last)
{
    int slot = blockIdx.x, b = blockIdx.y;
    int t = threadIdx.x, w = t >> 5, lane = t & 31;
    int sb = b*NSL + slot;

    __shared__ float u[64], p[64];
    __shared__ float xg[192], hg[192];
    __shared__ float snew[64], mn[64], hid[128], sfin[64], sq[64];
    __shared__ float stat[2];

    if (t < 64) {
        float S = g_S[sb];
        u[t] = g_U[sb*DD + t] / S;
        p[t] = g_slots[sb*DD + t];
    }
    __syncthreads();
    if (t < 64) g_U[sb*DD + t] = 0.f;
    if (t == 0) g_S[sb] = 0.f;

    float u_lo = u[lane], u_hi = u[lane+32];
    float p_lo = p[lane], p_hi = p[lane+32];
    #pragma unroll
    for (int it = 0; it < 12; it++) {
        int gd = w + 16*it;
        const float* wi = W_ih + gd*DD;
        const float* wh = W_hh + gd*DD;
        float xa = u_lo*wi[lane] + u_hi*wi[lane+32];
        float ha = p_lo*wh[lane] + p_hi*wh[lane+32];
        xa = wred(xa); ha = wred(ha);
        if (lane == 0) { xg[gd] = xa + b_ih[gd]; hg[gd] = ha + b_hh[gd]; }
    }
    __syncthreads();

    if (t < 64) {
        float r = 1.f/(1.f + expf(-(xg[t]      + hg[t])));
        float z = 1.f/(1.f + expf(-(xg[64+t]   + hg[64+t])));
        float n = tanhf(xg[128+t] + r*hg[128+t]);
        snew[t] = (1.f - z)*n + z*p[t];
    }
    __syncthreads();

    if (w == 0) {
        float a = snew[lane], c = snew[lane+32];
        float s  = wred(a + c);
        float ss = wred(a*a + c*c);
        if (lane == 0) {
            float mean = s*(1.f/64.f), var = ss*(1.f/64.f) - mean*mean;
            stat[0] = mean; stat[1] = rsqrtf(var + 1e-5f);
        }
    }
    __syncthreads();
    if (t < 64) mn[t] = (snew[t] - stat[0])*stat[1]*gml[t] + bml[t];
    __syncthreads();

    float m_lo = mn[lane], m_hi = mn[lane+32];
    #pragma unroll
    for (int it = 0; it < 8; it++) {
        int hh = w + 16*it;
        const float* w1 = mW1 + hh*DD;
        float a = m_lo*w1[lane] + m_hi*w1[lane+32];
        a = wred(a);
        if (lane == 0) hid[hh] = fmaxf(a + mb1[hh], 0.f);
    }
    __syncthreads();

    float h0 = hid[lane], h1 = hid[lane+32], h2 = hid[lane+64], h3 = hid[lane+96];
    #pragma unroll
    for (int it = 0; it < 4; it++) {
        int d = w + 16*it;
        const float* w2 = mW2 + d*HH;
        float a = h0*w2[lane] + h1*w2[lane+32] + h2*w2[lane+64] + h3*w2[lane+96];
        a = wred(a);
        if (lane == 0) {
            float vfin = snew[d] + a + mb2[d];
            sfin[d] = vfin;
            g_slots[sb*DD + d] = vfin;
            if (is_last) out[sb*DD + d] = vfin;
        }
    }
    __syncthreads();

    if (w == 0) {
        float a = sfin[lane], c = sfin[lane+32];
        float s  = wred(a + c);
        float ss = wred(a*a + c*c);
        if (lane == 0) {
            float mean = s*(1.f/64.f), var = ss*(1.f/64.f) - mean*mean;
            stat[0] = mean; stat[1] = rsqrtf(var + 1e-5f);
        }
    }
    __syncthreads();
    if (t < 64) sq[t] = (sfin[t] - stat[0])*stat[1]*gsl[t] + bsl[t];
    __syncthreads();

    float s_lo = sq[lane], s_hi = sq[lane+32];
    #pragma unroll
    for (int it = 0; it < 4; it++) {
        int d = w + 16*it;
        const float* wq = Wq + d*DD;
        float a = s_lo*wq[lane] + s_hi*wq[lane+32];
        a = wred(a);
        if (lane == 0) g_q[sb*DD + d] = (a + bq[d]) * 0.125f;
    }
}

// ============================================================
extern "C" void kernel_launch(void* const* d_in, const int* in_sizes, int n_in,
                              void* d_out, int out_size)
{
    const float* inputs = (const float*)d_in[0];
    const float* noise  = (const float*)d_in[1];
    const float* mu     = (const float*)d_in[2];
    const float* sigma  = (const float*)d_in[3];
    const float* Wq     = (const float*)d_in[4];
    const float* bq     = (const float*)d_in[5];
    const float* Wk     = (const float*)d_in[6];
    const float* bk     = (const float*)d_in[7];
    const float* Wv     = (const float*)d_in[8];
    const float* bv     = (const float*)d_in[9];
    const float* W_ih   = (const float*)d_in[10];
    const float* W_hh   = (const float*)d_in[11];
    const float* b_ih   = (const float*)d_in[12];
    const float* b_hh   = (const float*)d_in[13];
    const float* mW1    = (const float*)d_in[14];
    const float* mb1    = (const float*)d_in[15];
    const float* mW2    = (const float*)d_in[16];
    const float* mb2    = (const float*)d_in[17];
    const float* gin    = (const float*)d_in[18];
    const float* bin    = (const float*)d_in[19];
    const float* gsl    = (const float*)d_in[20];
    const float* bsl    = (const float*)d_in[21];
    const float* gml    = (const float*)d_in[22];
    const float* bml    = (const float*)d_in[23];
    float* out = (float*)d_out;

    const int PROJ_SMEM = 16960 * 4;
    static int attr_set = 0;
    if (!attr_set) {
        cudaFuncSetAttribute(proj_kernel, cudaFuncAttributeMaxDynamicSharedMemorySize, PROJ_SMEM);
        attr_set = 1;
    }

    proj_kernel<<<4096, 256, PROJ_SMEM>>>(inputs, Wk, bk, Wv, bv, gin, bin);   // launch 0
    prep_kernel<<<BB, 448>>>(noise, mu, sigma, Wq, bq, gsl, bsl);              // launch 1
    dummy_kernel<<<1, 32>>>();                                                 // launch 2 (shifts ncu capture to attn)
    for (int it = 0; it < 3; it++) {
        attn_kernel<<<dim3(32, BB), 256>>>();                                  // launches 3,5,7 -> ncu -s5 captures attn
        finish_kernel<<<dim3(NSL, BB), 512>>>(W_ih, W_hh, b_ih, b_hh, mW1, mb1, mW2, mb2,
                                              gml, bml, Wq, bq, gsl, bsl, out, (it == 2) ? 1 : 0);
    }
}